// round 10
// baseline (speedup 1.0000x reference)
#include <cuda_runtime.h>
#include <cuda_bf16.h>
#include <cstdint>

// ---------------------------------------------------------------------------
// MultiheadLocalAttentionV1: N=2, C=256, H=8, HD=32, 32x32 spatial,
// 15x15 window (225 taps), dilation 1, pad 7.
//
//   prep_all   : weight/qkv bf16-split fragments + Wrk/rel_v B-fragments
//   proj_gemm  : qp/kp/vp GEMM; K/V written pre-split bf16 hi/lo (V ch-major)
//   attn_mma   : local attention on tensor cores (dense-banded, split bf16)
//   prep_ao    : split attention output into A-fragment layout
//   final_gemm : out = ao @ Wp^T + bp
// ---------------------------------------------------------------------------

#define NB      2
#define HNUM    8
#define HDim    32
#define CCH     256
#define WDIM    32
#define HW      1024
#define WS      15
#define WS2     225
#define MAXDIS  7

#define TW      8
#define TH      2
#define TPIX    16
#define HR      16          // TH + 14
#define HC      22          // TW + 14
#define NHALO   352         // HR*HC, = 44 n8 tiles = 22 k16 tiles

#define T_CONST 5.656854249492381f
#define INV_T   0.17677669529663689f

#define OUT_ELEMS  (HW * NB * CCH)
#define ATTN_ELEMS (NB * HNUM * WS2 * HW)

// ---- attn smem layout (bytes) ----
// K halo [352][36] bf16 hi+lo  /  V^T [32][360] bf16 hi+lo  (same region)
#define SM_KHI   0
#define SM_KLO   25344                  // 352*36*2
#define SM_KEND  50688
// S dense [16][357] fp32  overlapped by  P hi/lo [16][360] bf16
#define SM_SS    50688
#define SM_PHI   50688
#define SM_PLO   62208                  // +16*360*2
#define SM_SEND  73728
// R / logits / probs [16][241] fp32
#define SM_SR    73728
#define SM_SQ    89152                  // Q [16][33] fp32 ; reused as partials
#define SMEM_ATTN 91264

#define SSTR 357
#define RSTR 241
#define QSTR 33
#define KROWU 18     // K halo row stride in u32 (36 bf16)
#define VROWU 180    // V^T / P row stride in u32 (360 bf16)

// fragment-array sizes (GEMM path)
#define AFRAGS  65536
#define BFRAGS  16384

// -------------------------- global scratch ---------------------------------
__device__ float g_qs[NB * HNUM * HW * HDim];       // scaled q (n,h,p,hd)
__device__ float g_ao[NB * HW * CCH];

__device__ uint4 g_Ahi[4 * AFRAGS];   // slots: 0=q 1=k 2=v 3=ao
__device__ uint4 g_Alo[4 * AFRAGS];
__device__ uint2 g_Bhi[4 * BFRAGS];   // slots: 0=WQ 1=WK 2=WV 3=Wp
__device__ uint2 g_Blo[4 * BFRAGS];

// pre-split K (hp-major pairs) and V (ch-major) for attention
__device__ uint32_t g_kbf_hi[NB * HNUM * HW * 16];
__device__ uint32_t g_kbf_lo[NB * HNUM * HW * 16];
__device__ __nv_bfloat16 g_vbf_hi[NB * HNUM * HDim * HW];
__device__ __nv_bfloat16 g_vbf_lo[NB * HNUM * HDim * HW];

// B-fragments for rel logits (T*Wrk) and rel_v
__device__ uint2 g_WrkFh[HNUM * 30 * 2 * 32];
__device__ uint2 g_WrkFl[HNUM * 30 * 2 * 32];
__device__ uint2 g_RvFh[HNUM * 4 * 15 * 32];
__device__ uint2 g_RvFl[HNUM * 4 * 15 * 32];

// ---------------------------------------------------------------------------
// bf16 helpers
// ---------------------------------------------------------------------------
__device__ __forceinline__ uint32_t pack2(float a, float b) {
    __nv_bfloat162 t = __floats2bfloat162_rn(a, b);  // .x = low half
    return *reinterpret_cast<uint32_t*>(&t);
}
__device__ __forceinline__ void split1(float x, float& hi, float& lo) {
    hi = __bfloat162float(__float2bfloat16(x));
    lo = x - hi;
}
__device__ __forceinline__ void mma_bf16(float* acc, uint4 a, uint2 b) {
    asm volatile(
        "mma.sync.aligned.m16n8k16.row.col.f32.bf16.bf16.f32 "
        "{%0,%1,%2,%3},{%4,%5,%6,%7},{%8,%9},{%0,%1,%2,%3};\n"
        : "+f"(acc[0]), "+f"(acc[1]), "+f"(acc[2]), "+f"(acc[3])
        : "r"(a.x), "r"(a.y), "r"(a.z), "r"(a.w), "r"(b.x), "r"(b.y));
}
// 3-MMA split product
__device__ __forceinline__ void mma3(float* acc, uint4 ah, uint4 al,
                                     uint2 bh, uint2 bl) {
    mma_bf16(acc, ah, bh);
    mma_bf16(acc, ah, bl);
    mma_bf16(acc, al, bh);
}

// ---------------------------------------------------------------------------
// prep_all:
//   blocks [0,256)      weight split  -> B fragments
//   blocks [256,1024)   q/k/v split   -> A fragments (slots 0-2)
//   blocks [1024,1084)  T*Wrk B-fragments per head
//   blocks [1084,1144)  rel_v B-fragments per head
// ---------------------------------------------------------------------------
__global__ __launch_bounds__(256) void prep_all(
    const float* __restrict__ q, const float* __restrict__ k,
    const float* __restrict__ v,
    const float* __restrict__ WQ, const float* __restrict__ WK,
    const float* __restrict__ WV, const float* __restrict__ Wp,
    const float* __restrict__ Wrk, const float* __restrict__ rel_v)
{
    const int b = blockIdx.x;

    if (b < 256) {
        int tid  = b * 256 + threadIdx.x;
        int lane = tid & 31;
        int k16  = (tid >> 5) & 15;
        int n8   = (tid >> 9) & 31;
        int mat  = tid >> 14;
        const float* W = (mat == 0) ? WQ : (mat == 1) ? WK : (mat == 2) ? WV : Wp;

        int g = lane >> 2, tig = lane & 3;
        int n  = n8 * 8 + g;
        int kb = k16 * 16 + 2 * tig;

        const float* r = W + (size_t)n * 256;
        float h0, l0, h1, l1, h8, l8, h9, l9;
        split1(r[kb],     h0, l0);
        split1(r[kb + 1], h1, l1);
        split1(r[kb + 8], h8, l8);
        split1(r[kb + 9], h9, l9);

        size_t idx = ((size_t)(mat * 32 + n8) * 16 + k16) * 32 + lane;
        g_Bhi[idx] = make_uint2(pack2(h0, h1), pack2(h8, h9));
        g_Blo[idx] = make_uint2(pack2(l0, l1), pack2(l8, l9));
    } else if (b < 1024) {
        int mat = (b - 256) >> 8;
        const float* src = (mat == 0) ? q : (mat == 1) ? k : v;

        int tid  = ((b - 256) & 255) * 256 + threadIdx.x;
        int lane = tid & 31;
        int k16  = (tid >> 5) & 15;
        int m16  = tid >> 9;
        int g = lane >> 2, tig = lane & 3;
        int r0 = m16 * 16 + g;
        int r1 = r0 + 8;
        int kb = k16 * 16 + 2 * tig;

        int n0 = r0 >> 10, p0 = r0 & 1023;
        int n1 = r1 >> 10, p1 = r1 & 1023;

        uint32_t hi[4], lo[4];
#pragma unroll
        for (int j = 0; j < 4; j++) {
            int row_n = (j & 1) ? n1 : n0;
            int row_p = (j & 1) ? p1 : p0;
            int kc = kb + ((j >> 1) ? 8 : 0);
            float f0 = src[((size_t)(row_n * 256 + kc)) * 1024 + row_p];
            float f1 = src[((size_t)(row_n * 256 + kc + 1)) * 1024 + row_p];
            float h0, l0, h1, l1;
            split1(f0, h0, l0);
            split1(f1, h1, l1);
            hi[j] = pack2(h0, h1);
            lo[j] = pack2(l0, l1);
        }
        size_t idx = (size_t)mat * AFRAGS + ((size_t)m16 * 16 + k16) * 32 + lane;
        g_Ahi[idx] = make_uint4(hi[0], hi[1], hi[2], hi[3]);
        g_Alo[idx] = make_uint4(lo[0], lo[1], lo[2], lo[3]);
    } else if (b < 1084) {
        // T*Wrk B-fragments: B[n = s240][k = ch]
        int i = (b - 1024) * 256 + threadIdx.x;   // < 15360
        int lane = i & 31;
        int k16  = (i >> 5) & 1;
        int rest = i >> 6;            // 0..239
        int n8 = rest % 30;
        int h  = rest / 30;
        int g = lane >> 2, tig = lane & 3;
        int s240 = n8 * 8 + g;
        int kh = s240 >> 4, kw = s240 & 15;
        int ch = 16 * k16 + 2 * tig;

        float v0 = 0.f, v1 = 0.f, v8 = 0.f, v9 = 0.f;
        if (kw < 15) {
            const float* wr = Wrk + ((size_t)(h * WS2 + kh * WS + kw)) * HDim;
            v0 = T_CONST * wr[ch];
            v1 = T_CONST * wr[ch + 1];
            v8 = T_CONST * wr[ch + 8];
            v9 = T_CONST * wr[ch + 9];
        }
        float h0, l0, h1, l1, h8, l8, h9, l9;
        split1(v0, h0, l0); split1(v1, h1, l1);
        split1(v8, h8, l8); split1(v9, h9, l9);
        size_t idx = ((size_t)(h * 30 + n8) * 2 + k16) * 32 + lane;
        g_WrkFh[idx] = make_uint2(pack2(h0, h1), pack2(h8, h9));
        g_WrkFl[idx] = make_uint2(pack2(l0, l1), pack2(l8, l9));
    } else {
        // rel_v B-fragments: B[n = ch][k = s240]
        int i = (b - 1084) * 256 + threadIdx.x;   // < 15360
        int lane = i & 31;
        int k16  = (i >> 5) % 15;
        int rest = i / (32 * 15);     // 0..31
        int nt = rest & 3;
        int h  = rest >> 2;
        int g = lane >> 2, tig = lane & 3;
        int ch = nt * 8 + g;
        int s0 = 16 * k16 + 2 * tig;

        const float* rv = rel_v + ((size_t)(h * HDim + ch)) * WS2;
        float vv[4];
#pragma unroll
        for (int j = 0; j < 4; j++) {
            int s240 = s0 + ((j >> 1) ? 8 : 0) + (j & 1);
            int kh = s240 >> 4, kw = s240 & 15;
            vv[j] = (kw < 15) ? rv[kh * WS + kw] : 0.f;
        }
        float h0, l0, h1, l1, h8, l8, h9, l9;
        split1(vv[0], h0, l0); split1(vv[1], h1, l1);
        split1(vv[2], h8, l8); split1(vv[3], h9, l9);
        size_t idx = ((size_t)(h * 4 + nt) * 15 + k16) * 32 + lane;
        g_RvFh[idx] = make_uint2(pack2(h0, h1), pack2(h8, h9));
        g_RvFl[idx] = make_uint2(pack2(l0, l1), pack2(l8, l9));
    }
}

// ---------------------------------------------------------------------------
// prep_ao: split g_ao into A-fragment slot 3.
// ---------------------------------------------------------------------------
__global__ __launch_bounds__(256) void prep_ao()
{
    int tid  = blockIdx.x * 256 + threadIdx.x;
    int lane = tid & 31;
    int k16  = (tid >> 5) & 15;
    int m16  = tid >> 9;
    int g = lane >> 2, tig = lane & 3;
    int r0 = m16 * 16 + g;
    int kb = k16 * 16 + 2 * tig;

    uint32_t hi[4], lo[4];
#pragma unroll
    for (int j = 0; j < 4; j++) {
        int row = r0 + ((j & 1) ? 8 : 0);
        int kc  = kb + ((j >> 1) ? 8 : 0);
        float2 f = *(const float2*)&g_ao[(size_t)row * 256 + kc];
        float h0, l0, h1, l1;
        split1(f.x, h0, l0);
        split1(f.y, h1, l1);
        hi[j] = pack2(h0, h1);
        lo[j] = pack2(l0, l1);
    }
    size_t idx = (size_t)3 * AFRAGS + ((size_t)m16 * 16 + k16) * 32 + lane;
    g_Ahi[idx] = make_uint4(hi[0], hi[1], hi[2], hi[3]);
    g_Alo[idx] = make_uint4(lo[0], lo[1], lo[2], lo[3]);
}

// ---------------------------------------------------------------------------
// GEMM core: warp computes 16m x 16n over K=256.
// ---------------------------------------------------------------------------
__device__ __forceinline__ void gemm_core(
    const uint4* __restrict__ Ahi, const uint4* __restrict__ Alo,
    const uint2* __restrict__ Bhi, const uint2* __restrict__ Blo,
    int m16, int n8b, int lane, float acc[2][4])
{
#pragma unroll 4
    for (int k16 = 0; k16 < 16; k16++) {
        uint4 ah = Ahi[((size_t)m16 * 16 + k16) * 32 + lane];
        uint4 al = Alo[((size_t)m16 * 16 + k16) * 32 + lane];
#pragma unroll
        for (int nt = 0; nt < 2; nt++) {
            size_t bi = ((size_t)(n8b + nt) * 16 + k16) * 32 + lane;
            mma3(acc[nt], ah, al, Bhi[bi], Blo[bi]);
        }
    }
}

// ---------------------------------------------------------------------------
// proj_gemm: grid (32, 16, 3), 128 threads.
//   mat 0 (Q): fp32 (n,h,p,hd) scaled by 1/T
//   mat 1 (K): bf16 hi/lo pairs, hp-major
//   mat 2 (V): bf16 hi/lo, ch-major (transposed)
// ---------------------------------------------------------------------------
__global__ __launch_bounds__(128) void proj_gemm(
    const float* __restrict__ bQ, const float* __restrict__ bK,
    const float* __restrict__ bV)
{
    const int mat  = blockIdx.z;
    const int warp = threadIdx.x >> 5;
    const int lane = threadIdx.x & 31;
    const int m16  = blockIdx.x * 4 + warp;
    const int n8b  = blockIdx.y * 2;

    const uint4* Ahi = g_Ahi + (size_t)mat * AFRAGS;
    const uint4* Alo = g_Alo + (size_t)mat * AFRAGS;
    const uint2* Bhi = g_Bhi + (size_t)mat * BFRAGS;
    const uint2* Blo = g_Blo + (size_t)mat * BFRAGS;

    float acc[2][4];
#pragma unroll
    for (int i = 0; i < 2; i++)
#pragma unroll
        for (int j = 0; j < 4; j++) acc[i][j] = 0.f;

    gemm_core(Ahi, Alo, Bhi, Blo, m16, n8b, lane, acc);

    const float* b = (mat == 0) ? bQ : (mat == 1) ? bK : bV;
    const int g = lane >> 2, tig = lane & 3;
    const int r0 = m16 * 16 + g;

#pragma unroll
    for (int nt = 0; nt < 2; nt++) {
        const int o0 = (n8b + nt) * 8 + 2 * tig;
        const int h = o0 >> 5, hd = o0 & 31;
        const float b0 = b[o0], b1 = b[o0 + 1];
#pragma unroll
        for (int rr = 0; rr < 2; rr++) {
            const int r = r0 + rr * 8;
            const int n_b = r >> 10, p = r & 1023;
            float vx = acc[nt][rr * 2]     + b0;
            float vy = acc[nt][rr * 2 + 1] + b1;
            if (mat == 0) {
                float2 val = make_float2(vx * INV_T, vy * INV_T);
                *(float2*)&g_qs[((size_t)(n_b * HNUM + h) * HW + p) * HDim + hd] = val;
            } else if (mat == 1) {
                float hx, lx, hy, ly;
                split1(vx, hx, lx);
                split1(vy, hy, ly);
                size_t u = ((size_t)(n_b * HNUM + h) * HW + p) * 16 + (hd >> 1);
                g_kbf_hi[u] = pack2(hx, hy);
                g_kbf_lo[u] = pack2(lx, ly);
            } else {
                float hx, lx, hy, ly;
                split1(vx, hx, lx);
                split1(vy, hy, ly);
                size_t base = ((size_t)(n_b * HNUM + h) * HDim + hd) * HW + p;
                g_vbf_hi[base]       = __float2bfloat16(hx);
                g_vbf_lo[base]       = __float2bfloat16(lx);
                g_vbf_hi[base + HW]  = __float2bfloat16(hy);
                g_vbf_lo[base + HW]  = __float2bfloat16(ly);
            }
        }
    }
}

// ---------------------------------------------------------------------------
// final_gemm: grid (32, 16), 128 threads. out[(p*NB+n)*256+o] = ao@Wp^T + bp
// ---------------------------------------------------------------------------
__global__ __launch_bounds__(128) void final_gemm(
    const float* __restrict__ bp, float* __restrict__ out)
{
    const int warp = threadIdx.x >> 5;
    const int lane = threadIdx.x & 31;
    const int m16  = blockIdx.x * 4 + warp;
    const int n8b  = blockIdx.y * 2;

    const uint4* Ahi = g_Ahi + (size_t)3 * AFRAGS;
    const uint4* Alo = g_Alo + (size_t)3 * AFRAGS;
    const uint2* Bhi = g_Bhi + (size_t)3 * BFRAGS;
    const uint2* Blo = g_Blo + (size_t)3 * BFRAGS;

    float acc[2][4];
#pragma unroll
    for (int i = 0; i < 2; i++)
#pragma unroll
        for (int j = 0; j < 4; j++) acc[i][j] = 0.f;

    gemm_core(Ahi, Alo, Bhi, Blo, m16, n8b, lane, acc);

    const int g = lane >> 2, tig = lane & 3;
    const int r0 = m16 * 16 + g;
#pragma unroll
    for (int nt = 0; nt < 2; nt++) {
        const int o0 = (n8b + nt) * 8 + 2 * tig;
        const float b0 = bp[o0], b1 = bp[o0 + 1];
#pragma unroll
        for (int rr = 0; rr < 2; rr++) {
            const int r = r0 + rr * 8;
            const int n_b = r >> 10, p = r & 1023;
            float2 val;
            val.x = acc[nt][rr * 2]     + b0;
            val.y = acc[nt][rr * 2 + 1] + b1;
            *(float2*)&out[((size_t)p * NB + n_b) * CCH + o0] = val;
        }
    }
}

// ---------------------------------------------------------------------------
// attn_mma: tensor-core local attention.
// grid = (64 tiles, 8 heads, 2 batch), 256 threads (8 warps), 2 CTA/SM.
// ---------------------------------------------------------------------------
extern __shared__ char smc[];

__global__ __launch_bounds__(256) void attn_mma(
    const float* __restrict__ brk, float* __restrict__ attn_out)
{
    const int h = blockIdx.y;
    const int n = blockIdx.z;
    const int tile = blockIdx.x;
    const int tx0 = (tile & 3) * TW;
    const int ty0 = (tile >> 2) * TH;
    const int t = threadIdx.x;
    const int w = t >> 5;
    const int lane = t & 31;
    const int g = lane >> 2, tig = lane & 3;
    const int nh = n * HNUM + h;

    uint32_t* kHiU = (uint32_t*)(smc + SM_KHI);
    uint32_t* kLoU = (uint32_t*)(smc + SM_KLO);
    uint32_t* vHiU = (uint32_t*)(smc + SM_KHI);   // V^T overlays K
    uint32_t* vLoU = (uint32_t*)(smc + SM_KLO);
    __nv_bfloat16* vHiB = (__nv_bfloat16*)(smc + SM_KHI);
    __nv_bfloat16* vLoB = (__nv_bfloat16*)(smc + SM_KLO);
    float*    sS  = (float*)(smc + SM_SS);
    uint32_t* pHiU = (uint32_t*)(smc + SM_PHI);
    uint32_t* pLoU = (uint32_t*)(smc + SM_PLO);
    __nv_bfloat16* pHiB = (__nv_bfloat16*)(smc + SM_PHI);
    __nv_bfloat16* pLoB = (__nv_bfloat16*)(smc + SM_PLO);
    float*    sR  = (float*)(smc + SM_SR);
    float*    sQ  = (float*)(smc + SM_SQ);
    float*    sPart = (float*)(smc + SM_SQ);      // reused in phase B

    // ---- load Q tile (fp32) ----
    for (int idx = t; idx < TPIX * 32; idx += 256) {
        int px = idx >> 5, c = idx & 31;
        int gp = (ty0 + (px >> 3)) * WDIM + tx0 + (px & 7);
        sQ[px * QSTR + c] = g_qs[((size_t)nh * HW + gp) * HDim + c];
    }
    // ---- load K halo bf16 hi/lo (zero padded) ----
    {
        const uint32_t* kh_hi = g_kbf_hi + (size_t)nh * HW * 16;
        const uint32_t* kh_lo = g_kbf_lo + (size_t)nh * HW * 16;
        for (int idx = t; idx < NHALO * 16; idx += 256) {
            int hp = idx >> 4, c2 = idx & 15;
            int hy = hp / HC, hx = hp - hy * HC;
            int gy = ty0 - MAXDIS + hy, gx = tx0 - MAXDIS + hx;
            uint32_t vh = 0, vl = 0;
            if ((unsigned)gy < 32u && (unsigned)gx < 32u) {
                size_t off = (size_t)(gy * WDIM + gx) * 16 + c2;
                vh = kh_hi[off];
                vl = kh_lo[off];
            }
            kHiU[hp * KROWU + c2] = vh;
            kLoU[hp * KROWU + c2] = vl;
        }
    }
    __syncthreads();

    // ---- build Q A-fragments (per warp, identical across warps) ----
    uint4 aQh[2], aQl[2];
#pragma unroll
    for (int k16 = 0; k16 < 2; k16++) {
        int kb = 16 * k16 + 2 * tig;
        float v00 = sQ[g * QSTR + kb],        v01 = sQ[g * QSTR + kb + 1];
        float v10 = sQ[(g + 8) * QSTR + kb],  v11 = sQ[(g + 8) * QSTR + kb + 1];
        float v08 = sQ[g * QSTR + kb + 8],    v09 = sQ[g * QSTR + kb + 9];
        float v18 = sQ[(g + 8) * QSTR + kb + 8], v19 = sQ[(g + 8) * QSTR + kb + 9];
        float h00,l00,h01,l01,h10,l10,h11,l11,h08,l08,h09,l09,h18,l18,h19,l19;
        split1(v00,h00,l00); split1(v01,h01,l01);
        split1(v10,h10,l10); split1(v11,h11,l11);
        split1(v08,h08,l08); split1(v09,h09,l09);
        split1(v18,h18,l18); split1(v19,h19,l19);
        aQh[k16] = make_uint4(pack2(h00,h01), pack2(h10,h11), pack2(h08,h09), pack2(h18,h19));
        aQl[k16] = make_uint4(pack2(l00,l01), pack2(l10,l11), pack2(l08,l09), pack2(l18,l19));
    }

    // ---- QK dense score GEMM: S[16][352] ----
    for (int n8 = w; n8 < 44; n8 += 8) {
        float acc[4] = {0.f, 0.f, 0.f, 0.f};
#pragma unroll
        for (int k16 = 0; k16 < 2; k16++) {
            int bi = (n8 * 8 + g) * KROWU + 8 * k16 + tig;
            uint2 bh = make_uint2(kHiU[bi], kHiU[bi + 4]);
            uint2 bl = make_uint2(kLoU[bi], kLoU[bi + 4]);
            mma3(acc, aQh[k16], aQl[k16], bh, bl);
        }
        int c0 = n8 * 8 + 2 * tig;
        sS[g * SSTR + c0]           = acc[0];
        sS[g * SSTR + c0 + 1]       = acc[1];
        sS[(g + 8) * SSTR + c0]     = acc[2];
        sS[(g + 8) * SSTR + c0 + 1] = acc[3];
    }
    // ---- rel logits GEMM: R[16][240] ----
    for (int n8 = w; n8 < 30; n8 += 8) {
        float acc[4] = {0.f, 0.f, 0.f, 0.f};
#pragma unroll
        for (int k16 = 0; k16 < 2; k16++) {
            size_t bi = ((size_t)(h * 30 + n8) * 2 + k16) * 32 + lane;
            mma3(acc, aQh[k16], aQl[k16], g_WrkFh[bi], g_WrkFl[bi]);
        }
        int c0 = n8 * 8 + 2 * tig;
        sR[g * RSTR + c0]           = acc[0];
        sR[g * RSTR + c0 + 1]       = acc[1];
        sR[(g + 8) * RSTR + c0]     = acc[2];
        sR[(g + 8) * RSTR + c0 + 1] = acc[3];
    }
    __syncthreads();

    // ---- banded extraction: L = S + R + brk - mask -> sR ----
    if (t < WS2) {
        const int s  = t;
        const int kh = s / WS;
        const int kw = s - kh * WS;
        const int aoff = kh * 16 + kw;
        const float bb = brk[h * WS2 + s];
#pragma unroll
        for (int px = 0; px < TPIX; px++) {
            const int py = px >> 3, pxx = px & 7;
            const int hp = (py + kh) * HC + pxx + kw;
            const int gy = ty0 + py + kh - MAXDIS;
            const int gx = tx0 + pxx + kw - MAXDIS;
            float a = sS[px * SSTR + hp] + sR[px * RSTR + aoff] + bb;
            if (!((unsigned)gy < 32u && (unsigned)gx < 32u)) a -= 1e8f;
            sR[px * RSTR + aoff] = a;
        }
    }
    __syncthreads();

    // ---- load V^T halo (overwrites K), zero P (overwrites S) ----
    {
        const __nv_bfloat16* vb_hi = g_vbf_hi + (size_t)nh * HDim * HW;
        const __nv_bfloat16* vb_lo = g_vbf_lo + (size_t)nh * HDim * HW;
        for (int idx = t; idx < 32 * NHALO; idx += 256) {
            int c = idx / NHALO, hp = idx - c * NHALO;
            int hy = hp / HC, hx = hp - hy * HC;
            int gy = ty0 - MAXDIS + hy, gx = tx0 - MAXDIS + hx;
            __nv_bfloat16 vh = __float2bfloat16(0.f), vl = vh;
            if ((unsigned)gy < 32u && (unsigned)gx < 32u) {
                size_t off = (size_t)c * HW + gy * WDIM + gx;
                vh = vb_hi[off];
                vl = vb_lo[off];
            }
            vHiB[c * 360 + hp] = vh;
            vLoB[c * 360 + hp] = vl;
        }
        // zero P region (pHi and pLo contiguous: 23040 B = 5760 u32)
        for (int idx = t; idx < 5760; idx += 256)
            pHiU[idx] = 0u;
    }

    // ---- softmax: warp handles 2 pixels ----
    {
#pragma unroll
        for (int pp = 0; pp < 2; pp++) {
            const int px = w * 2 + pp;
            float* arow = &sR[px * RSTR];
            if (lane < 15) arow[lane * 16 + 15] = 0.f;
            float vals[8];
            int   offs[8];
            float mx = -3.4e38f;
#pragma unroll
            for (int i = 0; i < 8; i++) {
                int s = lane + 32 * i;
                if (s < WS2) {
                    offs[i] = (s / WS) * 16 + (s % WS);
                    vals[i] = arow[offs[i]];
                } else { offs[i] = -1; vals[i] = -3.4e38f; }
                mx = fmaxf(mx, vals[i]);
            }
#pragma unroll
            for (int off = 16; off; off >>= 1)
                mx = fmaxf(mx, __shfl_xor_sync(0xffffffffu, mx, off));
            float sum = 0.f;
#pragma unroll
            for (int i = 0; i < 8; i++) {
                float e = (offs[i] >= 0) ? __expf(vals[i] - mx) : 0.f;
                vals[i] = e;
                sum += e;
            }
#pragma unroll
            for (int off = 16; off; off >>= 1)
                sum += __shfl_xor_sync(0xffffffffu, sum, off);
            const float inv = 1.0f / sum;
#pragma unroll
            for (int i = 0; i < 8; i++)
                if (offs[i] >= 0) arow[offs[i]] = vals[i] * inv;
        }
    }
    __syncthreads();

    // ---- write attn probabilities + scatter dense band P (bf16 split) ----
    if (attn_out) {
        float* ao = attn_out + (size_t)nh * WS2 * HW;
        for (int idx = t; idx < WS2 * TPIX; idx += 256) {
            int px = idx & 15, s = idx >> 4;
            int off = (s / WS) * 16 + (s % WS);
            int pgl = (ty0 + (px >> 3)) * WDIM + tx0 + (px & 7);
            ao[s * HW + pgl] = sR[px * RSTR + off];
        }
    }
    if (t < WS2) {
        const int s  = t;
        const int kh = s / WS;
        const int kw = s - kh * WS;
        const int aoff = kh * 16 + kw;
#pragma unroll
        for (int px = 0; px < TPIX; px++) {
            const int py = px >> 3, pxx = px & 7;
            const int hp = (py + kh) * HC + pxx + kw;
            float p = sR[px * RSTR + aoff];
            float hi, lo;
            split1(p, hi, lo);
            pHiB[px * 360 + hp] = __float2bfloat16(hi);
            pLoB[px * 360 + hp] = __float2bfloat16(lo);
        }
    }
    __syncthreads();

    // ---- phase B: out = P·V^T + probs·rel_v^T ; warp = (nt, khalf) ----
    {
        const int nt = w & 3;
        const int khalf = w >> 2;
        float acc[4] = {0.f, 0.f, 0.f, 0.f};

        // attn x V (dense over 352 halo = 22 k16)
        for (int k16 = khalf * 11; k16 < khalf * 11 + 11; k16++) {
            int r0i = g * VROWU + 8 * k16 + tig;
            int r1i = (g + 8) * VROWU + 8 * k16 + tig;
            uint4 ah = make_uint4(pHiU[r0i], pHiU[r1i], pHiU[r0i + 4], pHiU[r1i + 4]);
            uint4 al = make_uint4(pLoU[r0i], pLoU[r1i], pLoU[r0i + 4], pLoU[r1i + 4]);
            int bi = (nt * 8 + g) * VROWU + 8 * k16 + tig;
            uint2 bh = make_uint2(vHiU[bi], vHiU[bi + 4]);
            uint2 bl = make_uint2(vLoU[bi], vLoU[bi + 4]);
            mma3(acc, ah, al, bh, bl);
        }
        // probs x rel_v^T (240 = 15 k16)
        for (int k16 = khalf * 8; k16 < (khalf ? 15 : 8); k16++) {
            int kb = 16 * k16 + 2 * tig;
            float v00 = sR[g * RSTR + kb],        v01 = sR[g * RSTR + kb + 1];
            float v10 = sR[(g + 8) * RSTR + kb],  v11 = sR[(g + 8) * RSTR + kb + 1];
            float v08 = sR[g * RSTR + kb + 8],    v09 = sR[g * RSTR + kb + 9];
            float v18 = sR[(g + 8) * RSTR + kb + 8], v19 = sR[(g + 8) * RSTR + kb + 9];
            float h00,l00,h01,l01,h10,l10,h11,l11,h08,l08,h09,l09,h18,l18,h19,l19;
            split1(v00,h00,l00); split1(v01,h01,l01);
            split1(v10,h10,l10); split1(v11,h11,l11);
            split1(v08,h08,l08); split1(v09,h09,l09);
            split1(v18,h18,l18); split1(v19,h19,l19);
            uint4 ah = make_uint4(pack2(h00,h01), pack2(h10,h11), pack2(h08,h09), pack2(h18,h19));
            uint4 al = make_uint4(pack2(l00,l01), pack2(l10,l11), pack2(l08,l09), pack2(l18,l19));
            size_t bi = ((size_t)(h * 4 + nt) * 15 + k16) * 32 + lane;
            mma3(acc, ah, al, g_RvFh[bi], g_RvFl[bi]);
        }

        // combine the two k-halves
        const int ch0 = nt * 8 + 2 * tig;
        if (khalf == 1) {
            sPart[g * 32 + ch0]           = acc[0];
            sPart[g * 32 + ch0 + 1]       = acc[1];
            sPart[(g + 8) * 32 + ch0]     = acc[2];
            sPart[(g + 8) * 32 + ch0 + 1] = acc[3];
        }
        __syncthreads();
        if (khalf == 0) {
#pragma unroll
            for (int rr = 0; rr < 2; rr++) {
                const int px = g + rr * 8;
                const int gp = (ty0 + (px >> 3)) * WDIM + tx0 + (px & 7);
                float o0 = acc[rr * 2]     + sPart[px * 32 + ch0];
                float o1 = acc[rr * 2 + 1] + sPart[px * 32 + ch0 + 1];
                float2 val = make_float2(o0, o1);
                *(float2*)&g_ao[((size_t)n * HW + gp) * CCH + h * HDim + ch0] = val;
            }
        }
    }
}

// ---------------------------------------------------------------------------
extern "C" void kernel_launch(void* const* d_in, const int* in_sizes, int n_in,
                              void* d_out, int out_size)
{
    const float* q     = (const float*)d_in[0];
    const float* k     = (const float*)d_in[1];
    const float* v     = (const float*)d_in[2];
    const float* WQ    = (const float*)d_in[3];
    const float* bQ    = (const float*)d_in[4];
    const float* WK    = (const float*)d_in[5];
    const float* bK    = (const float*)d_in[6];
    const float* WV    = (const float*)d_in[7];
    const float* bV    = (const float*)d_in[8];
    const float* Wrk   = (const float*)d_in[9];
    const float* brk   = (const float*)d_in[10];
    const float* rel_v = (const float*)d_in[11];
    const float* Wp    = (const float*)d_in[12];
    const float* bp    = (const float*)d_in[13];

    float* out = (float*)d_out;
    float* attn_out = nullptr;
    if (out_size >= OUT_ELEMS + ATTN_ELEMS)
        attn_out = out + OUT_ELEMS;

    cudaFuncSetAttribute(attn_mma,
                         cudaFuncAttributeMaxDynamicSharedMemorySize, SMEM_ATTN);

    prep_all<<<1144, 256>>>(q, k, v, WQ, WK, WV, Wp, Wrk, rel_v);
    proj_gemm<<<dim3(32, 16, 3), 128>>>(bQ, bK, bV);
    attn_mma<<<dim3(64, HNUM, NB), 256, SMEM_ATTN>>>(brk, attn_out);
    prep_ao<<<256, 256>>>();
    final_gemm<<<dim3(32, 16), 128>>>(bp, out);
}

// round 12
// speedup vs baseline: 1.0474x; 1.0474x over previous
#include <cuda_runtime.h>
#include <cuda_bf16.h>
#include <cstdint>

// ---------------------------------------------------------------------------
// MultiheadLocalAttentionV1: N=2, C=256, H=8, HD=32, 32x32 spatial,
// 15x15 window (225 taps), dilation 1, pad 7.
//
//   prep_all   : split weights + q/k/v into bf16 hi/lo fragments, rel_v^T
//   proj_gemm  : qp/kp/vp = X@W^T + b via bf16 mma (2-way split, fp32 acc)
//   attn_kernel: local attention (fp32 SIMT, f32x2-packed logits,
//                epilogue scatters directly into final-GEMM A-fragments)
//   final_gemm : out = ao @ Wp^T + bp
// ---------------------------------------------------------------------------

#define NB      2
#define HNUM    8
#define HDim    32
#define CCH     256
#define WDIM    32
#define HW      1024
#define WS      15
#define WS2     225
#define MAXDIS  7

#define TW      8
#define TH      4
#define TPIX    32
#define HR      (TH + 14)   // 18
#define HC      (TW + 14)   // 22
#define NHALO   (HR * HC)   // 396
#define KSTR    36
#define ASTR    244

#define T_CONST 5.656854249492381f
#define INV_T   0.17677669529663689f

#define OUT_ELEMS  (HW * NB * CCH)
#define ATTN_ELEMS (NB * HNUM * WS2 * HW)

// attn smem layout (floats)
#define S_K 0
#define S_A (NHALO * KSTR)
#define S_Q (S_A + TPIX * ASTR)
#define SMEM_FLOATS (S_Q + TPIX * HDim)
#define SMEM_BYTES  (SMEM_FLOATS * 4)       // 92352 B

// fragment-array sizes
#define AFRAGS  65536   // per matrix: 128 m16 x 16 k16 x 32 lanes (uint4)
#define BFRAGS  16384   // per matrix: 32 n8 x 16 k16 x 32 lanes (uint2)

// -------------------------- global scratch ---------------------------------
__device__ float g_qs[NB * HNUM * HW * HDim];
__device__ float g_kp[NB * HNUM * HW * HDim];
__device__ float g_vp[NB * HNUM * HW * HDim];
__device__ float g_rvT[HNUM * WS2 * HDim];   // rel_v transposed (h,s,hd)

__device__ uint4 g_Ahi[4 * AFRAGS];   // slots: 0=q 1=k 2=v 3=ao
__device__ uint4 g_Alo[4 * AFRAGS];
__device__ uint2 g_Bhi[4 * BFRAGS];   // slots: 0=WQ 1=WK 2=WV 3=Wp
__device__ uint2 g_Blo[4 * BFRAGS];

// ---------------------------------------------------------------------------
// helpers
// ---------------------------------------------------------------------------
__device__ __forceinline__ uint32_t pack2(float a, float b) {
    __nv_bfloat162 t = __floats2bfloat162_rn(a, b);  // .x = low half
    return *reinterpret_cast<uint32_t*>(&t);
}
__device__ __forceinline__ void split1(float x, float& hi, float& lo) {
    hi = __bfloat162float(__float2bfloat16(x));
    lo = x - hi;
}
__device__ __forceinline__ void mma_bf16(float* acc, uint4 a, uint2 b) {
    asm volatile(
        "mma.sync.aligned.m16n8k16.row.col.f32.bf16.bf16.f32 "
        "{%0,%1,%2,%3},{%4,%5,%6,%7},{%8,%9},{%0,%1,%2,%3};\n"
        : "+f"(acc[0]), "+f"(acc[1]), "+f"(acc[2]), "+f"(acc[3])
        : "r"(a.x), "r"(a.y), "r"(a.z), "r"(a.w), "r"(b.x), "r"(b.y));
}

// packed fp32 pair ops (sm_100+)
__device__ __forceinline__ unsigned long long fma2(
    unsigned long long a, unsigned long long b, unsigned long long c) {
    unsigned long long d;
    asm("fma.rn.f32x2 %0, %1, %2, %3;" : "=l"(d) : "l"(a), "l"(b), "l"(c));
    return d;
}
__device__ __forceinline__ unsigned long long pk2f(float lo, float hi) {
    unsigned long long r;
    asm("mov.b64 %0, {%1, %2};" : "=l"(r) : "f"(lo), "f"(hi));
    return r;
}
__device__ __forceinline__ float hsum2(unsigned long long v) {
    float lo, hi;
    asm("mov.b64 {%0, %1}, %2;" : "=f"(lo), "=f"(hi) : "l"(v));
    return lo + hi;
}

// ---------------------------------------------------------------------------
// prep_all: blocks [0,256) weight split; [256,1024) q/k/v split;
//           [1024,1249) rel_v transpose
// ---------------------------------------------------------------------------
__global__ __launch_bounds__(256) void prep_all(
    const float* __restrict__ q, const float* __restrict__ k,
    const float* __restrict__ v,
    const float* __restrict__ WQ, const float* __restrict__ WK,
    const float* __restrict__ WV, const float* __restrict__ Wp,
    const float* __restrict__ rel_v)
{
    const int b = blockIdx.x;

    if (b < 256) {
        int tid  = b * 256 + threadIdx.x;
        int lane = tid & 31;
        int k16  = (tid >> 5) & 15;
        int n8   = (tid >> 9) & 31;
        int mat  = tid >> 14;
        const float* W = (mat == 0) ? WQ : (mat == 1) ? WK : (mat == 2) ? WV : Wp;

        int g = lane >> 2, tig = lane & 3;
        int n  = n8 * 8 + g;
        int kb = k16 * 16 + 2 * tig;

        const float* r = W + (size_t)n * 256;
        float h0, l0, h1, l1, h8, l8, h9, l9;
        split1(r[kb],     h0, l0);
        split1(r[kb + 1], h1, l1);
        split1(r[kb + 8], h8, l8);
        split1(r[kb + 9], h9, l9);

        size_t idx = ((size_t)(mat * 32 + n8) * 16 + k16) * 32 + lane;
        g_Bhi[idx] = make_uint2(pack2(h0, h1), pack2(h8, h9));
        g_Blo[idx] = make_uint2(pack2(l0, l1), pack2(l8, l9));
    } else if (b < 1024) {
        int mat = (b - 256) >> 8;
        const float* src = (mat == 0) ? q : (mat == 1) ? k : v;

        int tid  = ((b - 256) & 255) * 256 + threadIdx.x;
        int lane = tid & 31;
        int k16  = (tid >> 5) & 15;
        int m16  = tid >> 9;
        int g = lane >> 2, tig = lane & 3;
        int r0 = m16 * 16 + g;
        int r1 = r0 + 8;
        int kb = k16 * 16 + 2 * tig;

        int n0 = r0 >> 10, p0 = r0 & 1023;
        int n1 = r1 >> 10, p1 = r1 & 1023;

        uint32_t hi[4], lo[4];
#pragma unroll
        for (int j = 0; j < 4; j++) {
            int row_n = (j & 1) ? n1 : n0;
            int row_p = (j & 1) ? p1 : p0;
            int kc = kb + ((j >> 1) ? 8 : 0);
            float f0 = src[((size_t)(row_n * 256 + kc)) * 1024 + row_p];
            float f1 = src[((size_t)(row_n * 256 + kc + 1)) * 1024 + row_p];
            float h0, l0, h1, l1;
            split1(f0, h0, l0);
            split1(f1, h1, l1);
            hi[j] = pack2(h0, h1);
            lo[j] = pack2(l0, l1);
        }
        size_t idx = (size_t)mat * AFRAGS + ((size_t)m16 * 16 + k16) * 32 + lane;
        g_Ahi[idx] = make_uint4(hi[0], hi[1], hi[2], hi[3]);
        g_Alo[idx] = make_uint4(lo[0], lo[1], lo[2], lo[3]);
    } else {
        int i = (b - 1024) * 256 + threadIdx.x;
        if (i < HNUM * WS2 * HDim) {
            int c = i & 31;
            int s = (i >> 5) % WS2;
            int h = i / (WS2 * HDim);
            g_rvT[i] = rel_v[(h * HDim + c) * WS2 + s];
        }
    }
}

// ---------------------------------------------------------------------------
// GEMM core: warp computes 16m x 16n over K=256. No smem.
// ---------------------------------------------------------------------------
__device__ __forceinline__ void gemm_core(
    const uint4* __restrict__ Ahi, const uint4* __restrict__ Alo,
    const uint2* __restrict__ Bhi, const uint2* __restrict__ Blo,
    int m16, int n8b, int lane, float acc[2][4])
{
#pragma unroll 4
    for (int k16 = 0; k16 < 16; k16++) {
        uint4 ah = Ahi[((size_t)m16 * 16 + k16) * 32 + lane];
        uint4 al = Alo[((size_t)m16 * 16 + k16) * 32 + lane];
#pragma unroll
        for (int nt = 0; nt < 2; nt++) {
            size_t bi = ((size_t)(n8b + nt) * 16 + k16) * 32 + lane;
            uint2 bh = Bhi[bi];
            uint2 bl = Blo[bi];
            mma_bf16(acc[nt], ah, bh);
            mma_bf16(acc[nt], ah, bl);
            mma_bf16(acc[nt], al, bh);
        }
    }
}

// ---------------------------------------------------------------------------
// proj_gemm: grid (32, 16, 3), 128 threads. Writes (n,h,p,hd); q scaled 1/T.
// ---------------------------------------------------------------------------
__global__ __launch_bounds__(128) void proj_gemm(
    const float* __restrict__ bQ, const float* __restrict__ bK,
    const float* __restrict__ bV)
{
    const int mat  = blockIdx.z;
    const int warp = threadIdx.x >> 5;
    const int lane = threadIdx.x & 31;
    const int m16  = blockIdx.x * 4 + warp;
    const int n8b  = blockIdx.y * 2;

    const uint4* Ahi = g_Ahi + (size_t)mat * AFRAGS;
    const uint4* Alo = g_Alo + (size_t)mat * AFRAGS;
    const uint2* Bhi = g_Bhi + (size_t)mat * BFRAGS;
    const uint2* Blo = g_Blo + (size_t)mat * BFRAGS;

    float acc[2][4];
#pragma unroll
    for (int i = 0; i < 2; i++)
#pragma unroll
        for (int j = 0; j < 4; j++) acc[i][j] = 0.f;

    gemm_core(Ahi, Alo, Bhi, Blo, m16, n8b, lane, acc);

    const float* b = (mat == 0) ? bQ : (mat == 1) ? bK : bV;
    float* out     = (mat == 0) ? g_qs : (mat == 1) ? g_kp : g_vp;
    const float scale = (mat == 0) ? INV_T : 1.0f;

    const int g = lane >> 2, tig = lane & 3;
    const int r0 = m16 * 16 + g;
#pragma unroll
    for (int nt = 0; nt < 2; nt++) {
        const int o0 = (n8b + nt) * 8 + 2 * tig;
        const int h = o0 >> 5, hd = o0 & 31;
        const float b0 = b[o0], b1 = b[o0 + 1];
#pragma unroll
        for (int rr = 0; rr < 2; rr++) {
            const int r = r0 + rr * 8;
            const int n_b = r >> 10, p = r & 1023;
            float2 val;
            val.x = (acc[nt][rr * 2]     + b0) * scale;
            val.y = (acc[nt][rr * 2 + 1] + b1) * scale;
            *(float2*)&out[((size_t)(n_b * HNUM + h) * HW + p) * HDim + hd] = val;
        }
    }
}

// ---------------------------------------------------------------------------
// final_gemm: grid (32, 16), 128 threads. out[(p*NB+n)*256+o] = ao@Wp^T + bp
// ---------------------------------------------------------------------------
__global__ __launch_bounds__(128) void final_gemm(
    const float* __restrict__ bp, float* __restrict__ out)
{
    const int warp = threadIdx.x >> 5;
    const int lane = threadIdx.x & 31;
    const int m16  = blockIdx.x * 4 + warp;
    const int n8b  = blockIdx.y * 2;

    const uint4* Ahi = g_Ahi + (size_t)3 * AFRAGS;
    const uint4* Alo = g_Alo + (size_t)3 * AFRAGS;
    const uint2* Bhi = g_Bhi + (size_t)3 * BFRAGS;
    const uint2* Blo = g_Blo + (size_t)3 * BFRAGS;

    float acc[2][4];
#pragma unroll
    for (int i = 0; i < 2; i++)
#pragma unroll
        for (int j = 0; j < 4; j++) acc[i][j] = 0.f;

    gemm_core(Ahi, Alo, Bhi, Blo, m16, n8b, lane, acc);

    const int g = lane >> 2, tig = lane & 3;
    const int r0 = m16 * 16 + g;
#pragma unroll
    for (int nt = 0; nt < 2; nt++) {
        const int o0 = (n8b + nt) * 8 + 2 * tig;
        const float b0 = bp[o0], b1 = bp[o0 + 1];
#pragma unroll
        for (int rr = 0; rr < 2; rr++) {
            const int r = r0 + rr * 8;
            const int n_b = r >> 10, p = r & 1023;
            float2 val;
            val.x = acc[nt][rr * 2]     + b0;
            val.y = acc[nt][rr * 2 + 1] + b1;
            *(float2*)&out[((size_t)p * NB + n_b) * CCH + o0] = val;
        }
    }
}

// ---------------------------------------------------------------------------
// attn_kernel: local attention. grid = (32 tiles, 8 heads, 2 batch), 256 thr.
// ---------------------------------------------------------------------------
extern __shared__ float sm[];

__global__ __launch_bounds__(256) void attn_kernel(
    const float* __restrict__ Wrk, const float* __restrict__ brk,
    float* __restrict__ attn_out)
{
    const int h = blockIdx.y;
    const int n = blockIdx.z;
    const int tileIdx = blockIdx.x;
    const int tx0 = (tileIdx & 3) * TW;
    const int ty0 = (tileIdx >> 2) * TH;
    const int t = threadIdx.x;
    const int nh = n * HNUM + h;

    const float* qs = g_qs + (size_t)nh * HW * HDim;
    const float* kp = g_kp + (size_t)nh * HW * HDim;
    const float* vp = g_vp + (size_t)nh * HW * HDim;

    float* ksm  = sm + S_K;
    float* atsm = sm + S_A;
    float* qsm  = sm + S_Q;

    for (int idx = t; idx < TPIX * 32; idx += 256) {
        int px = idx >> 5, c = idx & 31;
        int gy = ty0 + (px >> 3), gx = tx0 + (px & 7);
        qsm[idx] = qs[(gy * WDIM + gx) * HDim + c];
    }
    for (int i4 = t; i4 < NHALO * 8; i4 += 256) {
        int hp = i4 >> 3, c4 = (i4 & 7) * 4;
        int hy = hp / HC, hx = hp - hy * HC;
        int gy = ty0 - MAXDIS + hy, gx = tx0 - MAXDIS + hx;
        float4 vv = make_float4(0.f, 0.f, 0.f, 0.f);
        if ((unsigned)gy < 32u && (unsigned)gx < 32u)
            vv = *(const float4*)&kp[(gy * WDIM + gx) * HDim + c4];
        *(float4*)&ksm[hp * KSTR + c4] = vv;
    }
    __syncthreads();

    // ---- logits: thread = tap s; f32x2 packed FMA, 2 px / iter ----
    if (t < WS2) {
        const int s  = t;
        const int kh = s / WS;
        const int kw = s - kh * WS;
        unsigned long long wp[16];
#pragma unroll
        for (int c4 = 0; c4 < 32; c4 += 4) {
            float4 w4 = *(const float4*)&Wrk[(h * WS2 + s) * HDim + c4];
            wp[(c4 >> 1)]     = pk2f(T_CONST * w4.x, T_CONST * w4.y);
            wp[(c4 >> 1) + 1] = pk2f(T_CONST * w4.z, T_CONST * w4.w);
        }
        const float bb = brk[h * WS2 + s];
        const int aoff = kh * 16 + kw;

#pragma unroll
        for (int py = 0; py < TH; py++) {
            const int gy = ty0 + py + kh - MAXDIS;
            const bool vy = ((unsigned)gy < 32u);
            const int hrow = (py + kh) * HC;
#pragma unroll
            for (int pp = 0; pp < TW; pp += 2) {
                const ulonglong2* k2a =
                    (const ulonglong2*)&ksm[(hrow + pp + kw) * KSTR];
                const ulonglong2* k2b =
                    (const ulonglong2*)&ksm[(hrow + pp + 1 + kw) * KSTR];
                const ulonglong2* q2a =
                    (const ulonglong2*)&qsm[(py * TW + pp) * 32];
                const ulonglong2* q2b = q2a + 8;   // next pixel (32 floats)
                unsigned long long aK0a = 0ull, aK0b = 0ull;
                unsigned long long aW0a = 0ull, aW0b = 0ull;
                unsigned long long aK1a = 0ull, aK1b = 0ull;
                unsigned long long aW1a = 0ull, aW1b = 0ull;
#pragma unroll
                for (int i = 0; i < 8; i++) {
                    ulonglong2 q0 = q2a[i];
                    ulonglong2 k0 = k2a[i];
                    ulonglong2 q1 = q2b[i];
                    ulonglong2 k1 = k2b[i];
                    aK0a = fma2(q0.x, k0.x, aK0a);
                    aK0b = fma2(q0.y, k0.y, aK0b);
                    aW0a = fma2(q0.x, wp[2 * i], aW0a);
                    aW0b = fma2(q0.y, wp[2 * i + 1], aW0b);
                    aK1a = fma2(q1.x, k1.x, aK1a);
                    aK1b = fma2(q1.y, k1.y, aK1b);
                    aW1a = fma2(q1.x, wp[2 * i], aW1a);
                    aW1b = fma2(q1.y, wp[2 * i + 1], aW1b);
                }
                float a0 = bb + hsum2(aK0a) + hsum2(aK0b)
                              + hsum2(aW0a) + hsum2(aW0b);
                float a1 = bb + hsum2(aK1a) + hsum2(aK1b)
                              + hsum2(aW1a) + hsum2(aW1b);
                const int gx0 = tx0 + pp + kw - MAXDIS;
                if (!(vy && (unsigned)gx0 < 32u))       a0 -= 1e8f;
                if (!(vy && (unsigned)(gx0 + 1) < 32u)) a1 -= 1e8f;
                atsm[(py * TW + pp) * ASTR + aoff]     = a0;
                atsm[(py * TW + pp + 1) * ASTR + aoff] = a1;
            }
        }
    }
    __syncthreads();

    // ---- overwrite halo with V ----
    for (int i4 = t; i4 < NHALO * 8; i4 += 256) {
        int hp = i4 >> 3, c4 = (i4 & 7) * 4;
        int hy = hp / HC, hx = hp - hy * HC;
        int gy = ty0 - MAXDIS + hy, gx = tx0 - MAXDIS + hx;
        float4 vv = make_float4(0.f, 0.f, 0.f, 0.f);
        if ((unsigned)gy < 32u && (unsigned)gx < 32u)
            vv = *(const float4*)&vp[(gy * WDIM + gx) * HDim + c4];
        *(float4*)&ksm[hp * KSTR + c4] = vv;
    }

    // ---- softmax: warp handles 4 pixels ----
    {
        const int warp = t >> 5, lane = t & 31;
#pragma unroll
        for (int pp = 0; pp < 4; pp++) {
            const int px = warp * 4 + pp;
            float* arow = &atsm[px * ASTR];
            if (lane < 15) arow[lane * 16 + 15] = 0.f;
            float vals[8];
            int   offs[8];
            float mx = -3.4e38f;
#pragma unroll
            for (int i = 0; i < 8; i++) {
                int s = lane + 32 * i;
                if (s < WS2) {
                    offs[i] = (s / WS) * 16 + (s % WS);
                    vals[i] = arow[offs[i]];
                } else { offs[i] = -1; vals[i] = -3.4e38f; }
                mx = fmaxf(mx, vals[i]);
            }
#pragma unroll
            for (int off = 16; off; off >>= 1)
                mx = fmaxf(mx, __shfl_xor_sync(0xffffffffu, mx, off));
            float sum = 0.f;
#pragma unroll
            for (int i = 0; i < 8; i++) {
                float e = (offs[i] >= 0) ? __expf(vals[i] - mx) : 0.f;
                vals[i] = e;
                sum += e;
            }
#pragma unroll
            for (int off = 16; off; off >>= 1)
                sum += __shfl_xor_sync(0xffffffffu, sum, off);
            const float inv = 1.0f / sum;
#pragma unroll
            for (int i = 0; i < 8; i++)
                if (offs[i] >= 0) arow[offs[i]] = vals[i] * inv;
        }
    }
    __syncthreads();

    // ---- write attn probabilities (n,H,WS2,hw) ----
    if (attn_out) {
        float* ao = attn_out + (size_t)nh * WS2 * HW;
        for (int idx = t; idx < WS2 * TPIX; idx += 256) {
            int px = idx & 31, s = idx >> 5;
            int off = (s / WS) * 16 + (s % WS);
            int pgl = (ty0 + (px >> 3)) * WDIM + tx0 + (px & 7);
            ao[s * HW + pgl] = atsm[px * ASTR + off];
        }
    }

    // ---- output: sliding-window regs; scatter into final-GEMM A-fragments --
    {
        const int c    = t & 31;
        const int warp = t >> 5;
        const int py   = warp & 3;
        const int half = warp >> 2;
        const int kh0  = half ? 8 : 0;
        const int kh1  = half ? 15 : 8;
        const float* rvh = g_rvT + (size_t)h * WS2 * HDim;

        float acc[TW];
#pragma unroll
        for (int i = 0; i < TW; i++) acc[i] = 0.f;

        for (int kh = kh0; kh < kh1; kh++) {
            const int hy = py + kh;
            float vreg[HC];
#pragma unroll
            for (int x = 0; x < HC; x++)
                vreg[x] = ksm[(hy * HC + x) * KSTR + c];
            float rreg[WS];
#pragma unroll
            for (int kw = 0; kw < WS; kw++)
                rreg[kw] = rvh[(kh * WS + kw) * HDim + c];

#pragma unroll
            for (int pxx = 0; pxx < TW; pxx++) {
                const float* arow = &atsm[(py * TW + pxx) * ASTR + kh * 16];
                float4 a0 = *(const float4*)(arow);
                float4 a1 = *(const float4*)(arow + 4);
                float4 a2 = *(const float4*)(arow + 8);
                float4 a3 = *(const float4*)(arow + 12);
                float av[15] = {a0.x, a0.y, a0.z, a0.w, a1.x, a1.y, a1.z, a1.w,
                                a2.x, a2.y, a2.z, a2.w, a3.x, a3.y, a3.z};
                float s0 = 0.f;
#pragma unroll
                for (int kw = 0; kw < WS; kw++) {
                    acc[pxx] += av[kw] * vreg[pxx + kw];
                    s0       += av[kw] * rreg[kw];
                }
                acc[pxx] += s0;
            }
        }

        if (half == 1) {
#pragma unroll
            for (int pxx = 0; pxx < TW; pxx++)
                qsm[(py * TW + pxx) * 32 + c] = acc[pxx];
        }
        __syncthreads();
        if (half == 0) {
            const int kglobal = h * 32 + c;
            const int k16  = kglobal >> 4;
            const int w16  = kglobal & 15;
            const int tigf = (w16 & 7) >> 1;
            const int jhi  = (w16 >> 3) & 1;
            uint32_t* AhiU = (uint32_t*)g_Ahi;
            uint32_t* AloU = (uint32_t*)g_Alo;
#pragma unroll
            for (int pxx = 0; pxx < TW; pxx++) {
                const int gy = ty0 + py, gx = tx0 + pxx;
                float tot = acc[pxx] + qsm[(py * TW + pxx) * 32 + c];
                float totN = __shfl_xor_sync(0xffffffffu, tot, 1);
                if ((c & 1) == 0) {
                    float hiE, loE, hiO, loO;
                    split1(tot,  hiE, loE);
                    split1(totN, hiO, loO);
                    const int m = n * HW + gy * WDIM + gx;
                    const int j = jhi * 2 + ((m >> 3) & 1);
                    const int lanef = (m & 7) * 4 + tigf;
                    const size_t u =
                        ((size_t)(3 * AFRAGS)
                         + ((size_t)(m >> 4) * 16 + k16) * 32 + lanef) * 4 + j;
                    AhiU[u] = pack2(hiE, hiO);
                    AloU[u] = pack2(loE, loO);
                }
            }
        }
    }
}

// ---------------------------------------------------------------------------
extern "C" void kernel_launch(void* const* d_in, const int* in_sizes, int n_in,
                              void* d_out, int out_size)
{
    const float* q     = (const float*)d_in[0];
    const float* k     = (const float*)d_in[1];
    const float* v     = (const float*)d_in[2];
    const float* WQ    = (const float*)d_in[3];
    const float* bQ    = (const float*)d_in[4];
    const float* WK    = (const float*)d_in[5];
    const float* bK    = (const float*)d_in[6];
    const float* WV    = (const float*)d_in[7];
    const float* bV    = (const float*)d_in[8];
    const float* Wrk   = (const float*)d_in[9];
    const float* brk   = (const float*)d_in[10];
    const float* rel_v = (const float*)d_in[11];
    const float* Wp    = (const float*)d_in[12];
    const float* bp    = (const float*)d_in[13];

    float* out = (float*)d_out;
    float* attn_out = nullptr;
    if (out_size >= OUT_ELEMS + ATTN_ELEMS)
        attn_out = out + OUT_ELEMS;

    cudaFuncSetAttribute(attn_kernel,
                         cudaFuncAttributeMaxDynamicSharedMemorySize, SMEM_BYTES);

    prep_all<<<1249, 256>>>(q, k, v, WQ, WK, WV, Wp, rel_v);
    proj_gemm<<<dim3(32, 16, 3), 128>>>(bQ, bK, bV);
    attn_kernel<<<dim3(32, HNUM, NB), 256, SMEM_BYTES>>>(Wrk, brk, attn_out);
    final_gemm<<<dim3(32, 16), 128>>>(bp, out);
}

// round 13
// speedup vs baseline: 1.1656x; 1.1128x over previous
#include <cuda_runtime.h>
#include <cuda_bf16.h>
#include <cstdint>

// ---------------------------------------------------------------------------
// MultiheadLocalAttentionV1: N=2, C=256, H=8, HD=32, 32x32 spatial,
// 15x15 window (225 taps), dilation 1, pad 7.
//
//   prep_all   : weight/qkv bf16-split fragments, T*Wrk B-fragments, rel_v^T
//   proj_gemm  : qp/kp/vp GEMM; K written pre-split bf16 hi/lo (hp-major)
//   attn_kernel: logits via bf16-split MMA (dense S + rel R, register scatter
//                into banded layout), fp32 softmax, SIMT sliding-window output,
//                epilogue scatters into final-GEMM A-fragments
//   final_gemm : out = ao @ Wp^T + bp
// ---------------------------------------------------------------------------

#define NB      2
#define HNUM    8
#define HDim    32
#define CCH     256
#define WDIM    32
#define HW      1024
#define WS      15
#define WS2     225
#define MAXDIS  7

#define TW      8
#define TH      4
#define TPIX    32
#define HR      (TH + 14)   // 18
#define HC      (TW + 14)   // 22
#define NHALO   (HR * HC)   // 396
#define NHALO_P 400         // padded to 50 n8-tiles
#define KSTR    36          // V overlay stride (floats)
#define ASTR    244
#define QSTR    33
#define KROWU   18          // K bf16 halo row stride in u32

#define T_CONST 5.656854249492381f
#define INV_T   0.17677669529663689f

#define OUT_ELEMS  (HW * NB * CCH)
#define ATTN_ELEMS (NB * HNUM * WS2 * HW)

// ---- attn smem layout (bytes) ----
// [0, 57600)       : K halo bf16 hi (400x18 u32) + lo ; later V fp32 [396][36]
// [57600, 88832)   : atsm [32][244] fp32
// [88832, 93056)   : sQ [32][33] fp32 ; later output partials [32][32]
#define SM_K    0
#define SM_KLO_U 7200        // u32 offset of lo region
#define SM_A    57600
#define SM_Q    88832
#define SMEM_ATTN 93056

// fragment-array sizes (GEMM path)
#define AFRAGS  65536   // per matrix: 128 m16 x 16 k16 x 32 lanes (uint4)
#define BFRAGS  16384   // per matrix: 32 n8 x 16 k16 x 32 lanes (uint2)

// -------------------------- global scratch ---------------------------------
__device__ float g_qs[NB * HNUM * HW * HDim];
__device__ float g_vp[NB * HNUM * HW * HDim];
__device__ float g_rvT[HNUM * WS2 * HDim];       // rel_v^T (h,s,hd)
__device__ uint32_t g_kbf_hi[NB * HNUM * HW * 16];   // K bf16 hi ch-pairs
__device__ uint32_t g_kbf_lo[NB * HNUM * HW * 16];

__device__ uint4 g_Ahi[4 * AFRAGS];   // slots: 0=q 1=k 2=v 3=ao
__device__ uint4 g_Alo[4 * AFRAGS];
__device__ uint2 g_Bhi[4 * BFRAGS];   // slots: 0=WQ 1=WK 2=WV 3=Wp
__device__ uint2 g_Blo[4 * BFRAGS];

// T*Wrk B-fragments: [h][30 n8][2 k16][32 lanes]
__device__ uint2 g_WrkFh[HNUM * 30 * 2 * 32];
__device__ uint2 g_WrkFl[HNUM * 30 * 2 * 32];

// ---------------------------------------------------------------------------
// helpers
// ---------------------------------------------------------------------------
__device__ __forceinline__ uint32_t pack2(float a, float b) {
    __nv_bfloat162 t = __floats2bfloat162_rn(a, b);  // .x = low half
    return *reinterpret_cast<uint32_t*>(&t);
}
__device__ __forceinline__ void split1(float x, float& hi, float& lo) {
    hi = __bfloat162float(__float2bfloat16(x));
    lo = x - hi;
}
__device__ __forceinline__ void mma_bf16(float* acc, uint4 a, uint2 b) {
    asm volatile(
        "mma.sync.aligned.m16n8k16.row.col.f32.bf16.bf16.f32 "
        "{%0,%1,%2,%3},{%4,%5,%6,%7},{%8,%9},{%0,%1,%2,%3};\n"
        : "+f"(acc[0]), "+f"(acc[1]), "+f"(acc[2]), "+f"(acc[3])
        : "r"(a.x), "r"(a.y), "r"(a.z), "r"(a.w), "r"(b.x), "r"(b.y));
}
__device__ __forceinline__ void mma3(float* acc, uint4 ah, uint4 al,
                                     uint2 bh, uint2 bl) {
    mma_bf16(acc, ah, bh);
    mma_bf16(acc, ah, bl);
    mma_bf16(acc, al, bh);
}

// ---------------------------------------------------------------------------
// prep_all: [0,256) weights; [256,1024) q/k/v; [1024,1084) T*Wrk frags;
//           [1084,1309) rel_v transpose
// ---------------------------------------------------------------------------
__global__ __launch_bounds__(256) void prep_all(
    const float* __restrict__ q, const float* __restrict__ k,
    const float* __restrict__ v,
    const float* __restrict__ WQ, const float* __restrict__ WK,
    const float* __restrict__ WV, const float* __restrict__ Wp,
    const float* __restrict__ Wrk, const float* __restrict__ rel_v)
{
    const int b = blockIdx.x;

    if (b < 256) {
        int tid  = b * 256 + threadIdx.x;
        int lane = tid & 31;
        int k16  = (tid >> 5) & 15;
        int n8   = (tid >> 9) & 31;
        int mat  = tid >> 14;
        const float* W = (mat == 0) ? WQ : (mat == 1) ? WK : (mat == 2) ? WV : Wp;

        int g = lane >> 2, tig = lane & 3;
        int n  = n8 * 8 + g;
        int kb = k16 * 16 + 2 * tig;

        const float* r = W + (size_t)n * 256;
        float h0, l0, h1, l1, h8, l8, h9, l9;
        split1(r[kb],     h0, l0);
        split1(r[kb + 1], h1, l1);
        split1(r[kb + 8], h8, l8);
        split1(r[kb + 9], h9, l9);

        size_t idx = ((size_t)(mat * 32 + n8) * 16 + k16) * 32 + lane;
        g_Bhi[idx] = make_uint2(pack2(h0, h1), pack2(h8, h9));
        g_Blo[idx] = make_uint2(pack2(l0, l1), pack2(l8, l9));
    } else if (b < 1024) {
        int mat = (b - 256) >> 8;
        const float* src = (mat == 0) ? q : (mat == 1) ? k : v;

        int tid  = ((b - 256) & 255) * 256 + threadIdx.x;
        int lane = tid & 31;
        int k16  = (tid >> 5) & 15;
        int m16  = tid >> 9;
        int g = lane >> 2, tig = lane & 3;
        int r0 = m16 * 16 + g;
        int r1 = r0 + 8;
        int kb = k16 * 16 + 2 * tig;

        int n0 = r0 >> 10, p0 = r0 & 1023;
        int n1 = r1 >> 10, p1 = r1 & 1023;

        uint32_t hi[4], lo[4];
#pragma unroll
        for (int j = 0; j < 4; j++) {
            int row_n = (j & 1) ? n1 : n0;
            int row_p = (j & 1) ? p1 : p0;
            int kc = kb + ((j >> 1) ? 8 : 0);
            float f0 = src[((size_t)(row_n * 256 + kc)) * 1024 + row_p];
            float f1 = src[((size_t)(row_n * 256 + kc + 1)) * 1024 + row_p];
            float h0, l0, h1, l1;
            split1(f0, h0, l0);
            split1(f1, h1, l1);
            hi[j] = pack2(h0, h1);
            lo[j] = pack2(l0, l1);
        }
        size_t idx = (size_t)mat * AFRAGS + ((size_t)m16 * 16 + k16) * 32 + lane;
        g_Ahi[idx] = make_uint4(hi[0], hi[1], hi[2], hi[3]);
        g_Alo[idx] = make_uint4(lo[0], lo[1], lo[2], lo[3]);
    } else if (b < 1084) {
        // T*Wrk B-fragments: B[n = s240 = kh*16+kw][k = ch] (kw=15 cols zero)
        int i = (b - 1024) * 256 + threadIdx.x;   // < 15360
        int lane = i & 31;
        int k16  = (i >> 5) & 1;
        int rest = i >> 6;            // 0..239
        int n8 = rest % 30;
        int h  = rest / 30;
        int g = lane >> 2, tig = lane & 3;
        int s240 = n8 * 8 + g;
        int kh = s240 >> 4, kw = s240 & 15;
        int ch = 16 * k16 + 2 * tig;

        float v0 = 0.f, v1 = 0.f, v8 = 0.f, v9 = 0.f;
        if (kw < 15) {
            const float* wr = Wrk + ((size_t)(h * WS2 + kh * WS + kw)) * HDim;
            v0 = T_CONST * wr[ch];
            v1 = T_CONST * wr[ch + 1];
            v8 = T_CONST * wr[ch + 8];
            v9 = T_CONST * wr[ch + 9];
        }
        float h0, l0, h1, l1, h8, l8, h9, l9;
        split1(v0, h0, l0); split1(v1, h1, l1);
        split1(v8, h8, l8); split1(v9, h9, l9);
        size_t idx = ((size_t)(h * 30 + n8) * 2 + k16) * 32 + lane;
        g_WrkFh[idx] = make_uint2(pack2(h0, h1), pack2(h8, h9));
        g_WrkFl[idx] = make_uint2(pack2(l0, l1), pack2(l8, l9));
    } else {
        int i = (b - 1084) * 256 + threadIdx.x;
        if (i < HNUM * WS2 * HDim) {
            int c = i & 31;
            int s = (i >> 5) % WS2;
            int h = i / (WS2 * HDim);
            g_rvT[i] = rel_v[(h * HDim + c) * WS2 + s];
        }
    }
}

// ---------------------------------------------------------------------------
// GEMM core: warp computes 16m x 16n over K=256. No smem.
// ---------------------------------------------------------------------------
__device__ __forceinline__ void gemm_core(
    const uint4* __restrict__ Ahi, const uint4* __restrict__ Alo,
    const uint2* __restrict__ Bhi, const uint2* __restrict__ Blo,
    int m16, int n8b, int lane, float acc[2][4])
{
#pragma unroll 4
    for (int k16 = 0; k16 < 16; k16++) {
        uint4 ah = Ahi[((size_t)m16 * 16 + k16) * 32 + lane];
        uint4 al = Alo[((size_t)m16 * 16 + k16) * 32 + lane];
#pragma unroll
        for (int nt = 0; nt < 2; nt++) {
            size_t bi = ((size_t)(n8b + nt) * 16 + k16) * 32 + lane;
            mma3(acc[nt], ah, al, Bhi[bi], Blo[bi]);
        }
    }
}

// ---------------------------------------------------------------------------
// proj_gemm: grid (32, 16, 3), 128 threads.
//   mat 0 (Q): fp32 (n,h,p,hd) scaled 1/T;  mat 1 (K): bf16 hi/lo pairs;
//   mat 2 (V): fp32 (n,h,p,hd)
// ---------------------------------------------------------------------------
__global__ __launch_bounds__(128) void proj_gemm(
    const float* __restrict__ bQ, const float* __restrict__ bK,
    const float* __restrict__ bV)
{
    const int mat  = blockIdx.z;
    const int warp = threadIdx.x >> 5;
    const int lane = threadIdx.x & 31;
    const int m16  = blockIdx.x * 4 + warp;
    const int n8b  = blockIdx.y * 2;

    const uint4* Ahi = g_Ahi + (size_t)mat * AFRAGS;
    const uint4* Alo = g_Alo + (size_t)mat * AFRAGS;
    const uint2* Bhi = g_Bhi + (size_t)mat * BFRAGS;
    const uint2* Blo = g_Blo + (size_t)mat * BFRAGS;

    float acc[2][4];
#pragma unroll
    for (int i = 0; i < 2; i++)
#pragma unroll
        for (int j = 0; j < 4; j++) acc[i][j] = 0.f;

    gemm_core(Ahi, Alo, Bhi, Blo, m16, n8b, lane, acc);

    const float* b = (mat == 0) ? bQ : (mat == 1) ? bK : bV;
    const int g = lane >> 2, tig = lane & 3;
    const int r0 = m16 * 16 + g;
#pragma unroll
    for (int nt = 0; nt < 2; nt++) {
        const int o0 = (n8b + nt) * 8 + 2 * tig;
        const int h = o0 >> 5, hd = o0 & 31;
        const float b0 = b[o0], b1 = b[o0 + 1];
#pragma unroll
        for (int rr = 0; rr < 2; rr++) {
            const int r = r0 + rr * 8;
            const int n_b = r >> 10, p = r & 1023;
            float vx = acc[nt][rr * 2]     + b0;
            float vy = acc[nt][rr * 2 + 1] + b1;
            if (mat == 0) {
                float2 val = make_float2(vx * INV_T, vy * INV_T);
                *(float2*)&g_qs[((size_t)(n_b * HNUM + h) * HW + p) * HDim + hd] = val;
            } else if (mat == 1) {
                float hx, lx, hy, ly;
                split1(vx, hx, lx);
                split1(vy, hy, ly);
                size_t u = ((size_t)(n_b * HNUM + h) * HW + p) * 16 + (hd >> 1);
                g_kbf_hi[u] = pack2(hx, hy);
                g_kbf_lo[u] = pack2(lx, ly);
            } else {
                float2 val = make_float2(vx, vy);
                *(float2*)&g_vp[((size_t)(n_b * HNUM + h) * HW + p) * HDim + hd] = val;
            }
        }
    }
}

// ---------------------------------------------------------------------------
// final_gemm: grid (32, 16), 128 threads. out[(p*NB+n)*256+o] = ao@Wp^T + bp
// ---------------------------------------------------------------------------
__global__ __launch_bounds__(128) void final_gemm(
    const float* __restrict__ bp, float* __restrict__ out)
{
    const int warp = threadIdx.x >> 5;
    const int lane = threadIdx.x & 31;
    const int m16  = blockIdx.x * 4 + warp;
    const int n8b  = blockIdx.y * 2;

    const uint4* Ahi = g_Ahi + (size_t)3 * AFRAGS;
    const uint4* Alo = g_Alo + (size_t)3 * AFRAGS;
    const uint2* Bhi = g_Bhi + (size_t)3 * BFRAGS;
    const uint2* Blo = g_Blo + (size_t)3 * BFRAGS;

    float acc[2][4];
#pragma unroll
    for (int i = 0; i < 2; i++)
#pragma unroll
        for (int j = 0; j < 4; j++) acc[i][j] = 0.f;

    gemm_core(Ahi, Alo, Bhi, Blo, m16, n8b, lane, acc);

    const int g = lane >> 2, tig = lane & 3;
    const int r0 = m16 * 16 + g;
#pragma unroll
    for (int nt = 0; nt < 2; nt++) {
        const int o0 = (n8b + nt) * 8 + 2 * tig;
        const float b0 = bp[o0], b1 = bp[o0 + 1];
#pragma unroll
        for (int rr = 0; rr < 2; rr++) {
            const int r = r0 + rr * 8;
            const int n_b = r >> 10, p = r & 1023;
            float2 val;
            val.x = acc[nt][rr * 2]     + b0;
            val.y = acc[nt][rr * 2 + 1] + b1;
            *(float2*)&out[((size_t)p * NB + n_b) * CCH + o0] = val;
        }
    }
}

// ---------------------------------------------------------------------------
// attn_kernel: grid (32 tiles, 8 heads, 2 batch), 256 threads (8 warps).
// ---------------------------------------------------------------------------
extern __shared__ char smc[];

__global__ __launch_bounds__(256) void attn_kernel(
    const float* __restrict__ brk, float* __restrict__ attn_out)
{
    const int h = blockIdx.y;
    const int n = blockIdx.z;
    const int tileIdx = blockIdx.x;
    const int tx0 = (tileIdx & 3) * TW;
    const int ty0 = (tileIdx >> 2) * TH;
    const int t = threadIdx.x;
    const int w = t >> 5;
    const int lane = t & 31;
    const int g = lane >> 2, tig = lane & 3;
    const int nh = n * HNUM + h;

    uint32_t* kHiU = (uint32_t*)(smc + SM_K);
    uint32_t* kLoU = kHiU + SM_KLO_U;
    float*    vsm  = (float*)(smc + SM_K);       // V fp32 overlay, stride 36
    float*    atsm = (float*)(smc + SM_A);
    float*    sQ   = (float*)(smc + SM_Q);
    float*    sPart = sQ;

    // ---- load Q tile + K bf16 halo (zero padded; rows 396-399 zero) ----
    for (int idx = t; idx < TPIX * 32; idx += 256) {
        int px = idx >> 5, c = idx & 31;
        int gp = (ty0 + (px >> 3)) * WDIM + tx0 + (px & 7);
        sQ[px * QSTR + c] = g_qs[((size_t)nh * HW + gp) * HDim + c];
    }
    {
        const uint32_t* kh_hi = g_kbf_hi + (size_t)nh * HW * 16;
        const uint32_t* kh_lo = g_kbf_lo + (size_t)nh * HW * 16;
        for (int idx = t; idx < NHALO_P * 16; idx += 256) {
            int hp = idx >> 4, c2 = idx & 15;
            uint32_t vh = 0, vl = 0;
            if (hp < NHALO) {
                int hy = hp / HC, hx = hp - hy * HC;
                int gy = ty0 - MAXDIS + hy, gx = tx0 - MAXDIS + hx;
                if ((unsigned)gy < 32u && (unsigned)gx < 32u) {
                    size_t off = (size_t)(gy * WDIM + gx) * 16 + c2;
                    vh = kh_hi[off];
                    vl = kh_lo[off];
                }
            }
            kHiU[hp * KROWU + c2] = vh;
            kLoU[hp * KROWU + c2] = vl;
        }
    }
    __syncthreads();

    // ---- build Q A-fragments: 2 m16 x 2 k16 ----
    uint4 aQh[2][2], aQl[2][2];
#pragma unroll
    for (int m16 = 0; m16 < 2; m16++) {
#pragma unroll
        for (int k16 = 0; k16 < 2; k16++) {
            int rb = m16 * 16 + g;
            int kb = 16 * k16 + 2 * tig;
            float v00 = sQ[rb * QSTR + kb],            v01 = sQ[rb * QSTR + kb + 1];
            float v10 = sQ[(rb + 8) * QSTR + kb],      v11 = sQ[(rb + 8) * QSTR + kb + 1];
            float v08 = sQ[rb * QSTR + kb + 8],        v09 = sQ[rb * QSTR + kb + 9];
            float v18 = sQ[(rb + 8) * QSTR + kb + 8],  v19 = sQ[(rb + 8) * QSTR + kb + 9];
            float h00,l00,h01,l01,h10,l10,h11,l11,h08,l08,h09,l09,h18,l18,h19,l19;
            split1(v00,h00,l00); split1(v01,h01,l01);
            split1(v10,h10,l10); split1(v11,h11,l11);
            split1(v08,h08,l08); split1(v09,h09,l09);
            split1(v18,h18,l18); split1(v19,h19,l19);
            aQh[m16][k16] = make_uint4(pack2(h00,h01), pack2(h10,h11),
                                       pack2(h08,h09), pack2(h18,h19));
            aQl[m16][k16] = make_uint4(pack2(l00,l01), pack2(l10,l11),
                                       pack2(l08,l09), pack2(l18,l19));
        }
    }

    // ---- phase R: rel logits GEMM -> atsm (cols are already kh*16+kw) ----
    for (int n8 = w; n8 < 30; n8 += 8) {
        float acc[2][4];
#pragma unroll
        for (int i = 0; i < 2; i++)
#pragma unroll
            for (int j = 0; j < 4; j++) acc[i][j] = 0.f;
#pragma unroll
        for (int k16 = 0; k16 < 2; k16++) {
            size_t bi = ((size_t)(h * 30 + n8) * 2 + k16) * 32 + lane;
            uint2 bh = g_WrkFh[bi];
            uint2 bl = g_WrkFl[bi];
            mma3(acc[0], aQh[0][k16], aQl[0][k16], bh, bl);
            mma3(acc[1], aQh[1][k16], aQl[1][k16], bh, bl);
        }
        const int c0 = n8 * 8 + 2 * tig;
        const int kh = c0 >> 4, kw = c0 & 15;
        float bb0 = (kw < 15) ? brk[h * WS2 + kh * WS + kw] : 0.f;
        float bb1 = (kw < 14) ? brk[h * WS2 + kh * WS + kw + 1] : 0.f;
#pragma unroll
        for (int m16 = 0; m16 < 2; m16++) {
            const int rb = m16 * 16 + g;
            atsm[rb * ASTR + c0]           = acc[m16][0] + bb0;
            atsm[rb * ASTR + c0 + 1]       = acc[m16][1] + bb1;
            atsm[(rb + 8) * ASTR + c0]     = acc[m16][2] + bb0;
            atsm[(rb + 8) * ASTR + c0 + 1] = acc[m16][3] + bb1;
        }
    }
    __syncthreads();

    // ---- phase S: dense QK GEMM + banded scatter (RMW into atsm) ----
    for (int n8 = w; n8 < 50; n8 += 8) {
        float acc[2][4];
#pragma unroll
        for (int i = 0; i < 2; i++)
#pragma unroll
            for (int j = 0; j < 4; j++) acc[i][j] = 0.f;
#pragma unroll
        for (int k16 = 0; k16 < 2; k16++) {
            int bi = (n8 * 8 + g) * KROWU + 8 * k16 + tig;
            uint2 bh = make_uint2(kHiU[bi], kHiU[bi + 4]);
            uint2 bl = make_uint2(kLoU[bi], kLoU[bi + 4]);
            mma3(acc[0], aQh[0][k16], aQl[0][k16], bh, bl);
            mma3(acc[1], aQh[1][k16], aQl[1][k16], bh, bl);
        }
        const int c0 = n8 * 8 + 2 * tig;
#pragma unroll
        for (int m16 = 0; m16 < 2; m16++) {
#pragma unroll
            for (int j = 0; j < 4; j++) {
                const int row = m16 * 16 + g + ((j >> 1) ? 8 : 0);
                const int cc  = c0 + (j & 1);
                if (cc < NHALO) {
                    const int hy = cc / HC, hx = cc - hy * HC;
                    const int py = row >> 3, pxx = row & 7;
                    const int kh = hy - py, kw = hx - pxx;
                    if ((unsigned)kh < 15u && (unsigned)kw < 15u) {
                        const int gy = ty0 + hy - MAXDIS;
                        const int gx = tx0 + hx - MAXDIS;
                        const int idx = row * ASTR + kh * 16 + kw;
                        float a = atsm[idx] + acc[m16][j];
                        if (!((unsigned)gy < 32u && (unsigned)gx < 32u))
                            a -= 1e8f;
                        atsm[idx] = a;
                    }
                }
            }
        }
    }
    __syncthreads();

    // ---- load V fp32 (overwrites K region; stride 36) ----
    for (int i4 = t; i4 < NHALO * 8; i4 += 256) {
        int hp = i4 >> 3, c4 = (i4 & 7) * 4;
        int hy = hp / HC, hx = hp - hy * HC;
        int gy = ty0 - MAXDIS + hy, gx = tx0 - MAXDIS + hx;
        float4 vv = make_float4(0.f, 0.f, 0.f, 0.f);
        if ((unsigned)gy < 32u && (unsigned)gx < 32u)
            vv = *(const float4*)&g_vp[((size_t)nh * HW + gy * WDIM + gx) * HDim + c4];
        *(float4*)&vsm[hp * KSTR + c4] = vv;
    }

    // ---- softmax: warp handles 4 pixels ----
    {
#pragma unroll
        for (int pp = 0; pp < 4; pp++) {
            const int px = w * 4 + pp;
            float* arow = &atsm[px * ASTR];
            if (lane < 15) arow[lane * 16 + 15] = 0.f;
            float vals[8];
            int   offs[8];
            float mx = -3.4e38f;
#pragma unroll
            for (int i = 0; i < 8; i++) {
                int s = lane + 32 * i;
                if (s < WS2) {
                    offs[i] = (s / WS) * 16 + (s % WS);
                    vals[i] = arow[offs[i]];
                } else { offs[i] = -1; vals[i] = -3.4e38f; }
                mx = fmaxf(mx, vals[i]);
            }
#pragma unroll
            for (int off = 16; off; off >>= 1)
                mx = fmaxf(mx, __shfl_xor_sync(0xffffffffu, mx, off));
            float sum = 0.f;
#pragma unroll
            for (int i = 0; i < 8; i++) {
                float e = (offs[i] >= 0) ? __expf(vals[i] - mx) : 0.f;
                vals[i] = e;
                sum += e;
            }
#pragma unroll
            for (int off = 16; off; off >>= 1)
                sum += __shfl_xor_sync(0xffffffffu, sum, off);
            const float inv = 1.0f / sum;
#pragma unroll
            for (int i = 0; i < 8; i++)
                if (offs[i] >= 0) arow[offs[i]] = vals[i] * inv;
        }
    }
    __syncthreads();

    // ---- write attn probabilities (n,H,WS2,hw) ----
    if (attn_out) {
        float* ao = attn_out + (size_t)nh * WS2 * HW;
        for (int idx = t; idx < WS2 * TPIX; idx += 256) {
            int px = idx & 31, s = idx >> 5;
            int off = (s / WS) * 16 + (s % WS);
            int pgl = (ty0 + (px >> 3)) * WDIM + tx0 + (px & 7);
            ao[s * HW + pgl] = atsm[px * ASTR + off];
        }
    }

    // ---- output: sliding-window regs; scatter into final-GEMM A-fragments --
    {
        const int c    = t & 31;
        const int warp = t >> 5;
        const int py   = warp & 3;
        const int half = warp >> 2;
        const int kh0  = half ? 8 : 0;
        const int kh1  = half ? 15 : 8;
        const float* rvh = g_rvT + (size_t)h * WS2 * HDim;

        float acc[TW];
#pragma unroll
        for (int i = 0; i < TW; i++) acc[i] = 0.f;

        for (int kh = kh0; kh < kh1; kh++) {
            const int hy = py + kh;
            float vreg[HC];
#pragma unroll
            for (int x = 0; x < HC; x++)
                vreg[x] = vsm[(hy * HC + x) * KSTR + c];
            float rreg[WS];
#pragma unroll
            for (int kw = 0; kw < WS; kw++)
                rreg[kw] = rvh[(kh * WS + kw) * HDim + c];

#pragma unroll
            for (int pxx = 0; pxx < TW; pxx++) {
                const float* arow = &atsm[(py * TW + pxx) * ASTR + kh * 16];
                float4 a0 = *(const float4*)(arow);
                float4 a1 = *(const float4*)(arow + 4);
                float4 a2 = *(const float4*)(arow + 8);
                float4 a3 = *(const float4*)(arow + 12);
                float av[15] = {a0.x, a0.y, a0.z, a0.w, a1.x, a1.y, a1.z, a1.w,
                                a2.x, a2.y, a2.z, a2.w, a3.x, a3.y, a3.z};
                float s0 = 0.f;
#pragma unroll
                for (int kw = 0; kw < WS; kw++) {
                    acc[pxx] += av[kw] * vreg[pxx + kw];
                    s0       += av[kw] * rreg[kw];
                }
                acc[pxx] += s0;
            }
        }

        if (half == 1) {
#pragma unroll
            for (int pxx = 0; pxx < TW; pxx++)
                sPart[(py * TW + pxx) * 32 + c] = acc[pxx];
        }
        __syncthreads();
        if (half == 0) {
            const int kglobal = h * 32 + c;
            const int k16  = kglobal >> 4;
            const int w16  = kglobal & 15;
            const int tigf = (w16 & 7) >> 1;
            const int jhi  = (w16 >> 3) & 1;
            uint32_t* AhiU = (uint32_t*)g_Ahi;
            uint32_t* AloU = (uint32_t*)g_Alo;
#pragma unroll
            for (int pxx = 0; pxx < TW; pxx++) {
                const int gy = ty0 + py, gx = tx0 + pxx;
                float tot = acc[pxx] + sPart[(py * TW + pxx) * 32 + c];
                float totN = __shfl_xor_sync(0xffffffffu, tot, 1);
                if ((c & 1) == 0) {
                    float hiE, loE, hiO, loO;
                    split1(tot,  hiE, loE);
                    split1(totN, hiO, loO);
                    const int m = n * HW + gy * WDIM + gx;
                    const int j = jhi * 2 + ((m >> 3) & 1);
                    const int lanef = (m & 7) * 4 + tigf;
                    const size_t u =
                        ((size_t)(3 * AFRAGS)
                         + ((size_t)(m >> 4) * 16 + k16) * 32 + lanef) * 4 + j;
                    AhiU[u] = pack2(hiE, hiO);
                    AloU[u] = pack2(loE, loO);
                }
            }
        }
    }
}

// ---------------------------------------------------------------------------
extern "C" void kernel_launch(void* const* d_in, const int* in_sizes, int n_in,
                              void* d_out, int out_size)
{
    const float* q     = (const float*)d_in[0];
    const float* k     = (const float*)d_in[1];
    const float* v     = (const float*)d_in[2];
    const float* WQ    = (const float*)d_in[3];
    const float* bQ    = (const float*)d_in[4];
    const float* WK    = (const float*)d_in[5];
    const float* bK    = (const float*)d_in[6];
    const float* WV    = (const float*)d_in[7];
    const float* bV    = (const float*)d_in[8];
    const float* Wrk   = (const float*)d_in[9];
    const float* brk   = (const float*)d_in[10];
    const float* rel_v = (const float*)d_in[11];
    const float* Wp    = (const float*)d_in[12];
    const float* bp    = (const float*)d_in[13];

    float* out = (float*)d_out;
    float* attn_out = nullptr;
    if (out_size >= OUT_ELEMS + ATTN_ELEMS)
        attn_out = out + OUT_ELEMS;

    cudaFuncSetAttribute(attn_kernel,
                         cudaFuncAttributeMaxDynamicSharedMemorySize, SMEM_ATTN);

    prep_all<<<1309, 256>>>(q, k, v, WQ, WK, WV, Wp, Wrk, rel_v);
    proj_gemm<<<dim3(32, 16, 3), 128>>>(bQ, bK, bV);
    attn_kernel<<<dim3(32, HNUM, NB), 256, SMEM_ATTN>>>(brk, attn_out);
    final_gemm<<<dim3(32, 16), 128>>>(bp, out);
}

// round 14
// speedup vs baseline: 1.2198x; 1.0465x over previous
#include <cuda_runtime.h>
#include <cuda_bf16.h>
#include <cstdint>

// ---------------------------------------------------------------------------
// MultiheadLocalAttentionV1: N=2, C=256, H=8, HD=32, 32x32 spatial,
// 15x15 window (225 taps), dilation 1, pad 7.
//
//   prep_all   : weight/qkv bf16-split fragments, T*Wrk B-fragments, rel_v^T
//   proj_gemm  : split-K (2 halves/block) bf16 mma GEMM; K pre-split bf16
//   attn_kernel: MMA logits + fp32 softmax + SIMT sliding-window output,
//                epilogue scatters into final-GEMM A-fragments
//   final_gemm : split-K bf16 mma GEMM, out = ao @ Wp^T + bp
// ---------------------------------------------------------------------------

#define NB      2
#define HNUM    8
#define HDim    32
#define CCH     256
#define WDIM    32
#define HW      1024
#define WS      15
#define WS2     225
#define MAXDIS  7

#define TW      8
#define TH      4
#define TPIX    32
#define HR      (TH + 14)   // 18
#define HC      (TW + 14)   // 22
#define NHALO   (HR * HC)   // 396
#define NHALO_P 400
#define KSTR    36
#define ASTR    244
#define QSTR    33
#define KROWU   18

#define T_CONST 5.656854249492381f
#define INV_T   0.17677669529663689f

#define OUT_ELEMS  (HW * NB * CCH)
#define ATTN_ELEMS (NB * HNUM * WS2 * HW)

// attn smem layout (bytes)
#define SM_K    0
#define SM_KLO_U 7200
#define SM_A    57600
#define SM_Q    88832
#define SMEM_ATTN 93056

#define AFRAGS  65536
#define BFRAGS  16384

// -------------------------- global scratch ---------------------------------
__device__ float g_qs[NB * HNUM * HW * HDim];
__device__ float g_vp[NB * HNUM * HW * HDim];
__device__ float g_rvT[HNUM * WS2 * HDim];
__device__ uint32_t g_kbf_hi[NB * HNUM * HW * 16];
__device__ uint32_t g_kbf_lo[NB * HNUM * HW * 16];

__device__ uint4 g_Ahi[4 * AFRAGS];   // slots: 0=q 1=k 2=v 3=ao
__device__ uint4 g_Alo[4 * AFRAGS];
__device__ uint2 g_Bhi[4 * BFRAGS];   // slots: 0=WQ 1=WK 2=WV 3=Wp
__device__ uint2 g_Blo[4 * BFRAGS];

__device__ uint2 g_WrkFh[HNUM * 30 * 2 * 32];
__device__ uint2 g_WrkFl[HNUM * 30 * 2 * 32];

// ---------------------------------------------------------------------------
// helpers
// ---------------------------------------------------------------------------
__device__ __forceinline__ uint32_t pack2(float a, float b) {
    __nv_bfloat162 t = __floats2bfloat162_rn(a, b);
    return *reinterpret_cast<uint32_t*>(&t);
}
__device__ __forceinline__ void split1(float x, float& hi, float& lo) {
    hi = __bfloat162float(__float2bfloat16(x));
    lo = x - hi;
}
__device__ __forceinline__ void mma_bf16(float* acc, uint4 a, uint2 b) {
    asm volatile(
        "mma.sync.aligned.m16n8k16.row.col.f32.bf16.bf16.f32 "
        "{%0,%1,%2,%3},{%4,%5,%6,%7},{%8,%9},{%0,%1,%2,%3};\n"
        : "+f"(acc[0]), "+f"(acc[1]), "+f"(acc[2]), "+f"(acc[3])
        : "r"(a.x), "r"(a.y), "r"(a.z), "r"(a.w), "r"(b.x), "r"(b.y));
}
__device__ __forceinline__ void mma3(float* acc, uint4 ah, uint4 al,
                                     uint2 bh, uint2 bl) {
    mma_bf16(acc, ah, bh);
    mma_bf16(acc, ah, bl);
    mma_bf16(acc, al, bh);
}

// ---------------------------------------------------------------------------
// prep_all: [0,256) weights; [256,1024) q/k/v; [1024,1084) T*Wrk frags;
//           [1084,1309) rel_v transpose
// ---------------------------------------------------------------------------
__global__ __launch_bounds__(256) void prep_all(
    const float* __restrict__ q, const float* __restrict__ k,
    const float* __restrict__ v,
    const float* __restrict__ WQ, const float* __restrict__ WK,
    const float* __restrict__ WV, const float* __restrict__ Wp,
    const float* __restrict__ Wrk, const float* __restrict__ rel_v)
{
    const int b = blockIdx.x;

    if (b < 256) {
        int tid  = b * 256 + threadIdx.x;
        int lane = tid & 31;
        int k16  = (tid >> 5) & 15;
        int n8   = (tid >> 9) & 31;
        int mat  = tid >> 14;
        const float* W = (mat == 0) ? WQ : (mat == 1) ? WK : (mat == 2) ? WV : Wp;

        int g = lane >> 2, tig = lane & 3;
        int n  = n8 * 8 + g;
        int kb = k16 * 16 + 2 * tig;

        const float* r = W + (size_t)n * 256;
        float h0, l0, h1, l1, h8, l8, h9, l9;
        split1(r[kb],     h0, l0);
        split1(r[kb + 1], h1, l1);
        split1(r[kb + 8], h8, l8);
        split1(r[kb + 9], h9, l9);

        size_t idx = ((size_t)(mat * 32 + n8) * 16 + k16) * 32 + lane;
        g_Bhi[idx] = make_uint2(pack2(h0, h1), pack2(h8, h9));
        g_Blo[idx] = make_uint2(pack2(l0, l1), pack2(l8, l9));
    } else if (b < 1024) {
        int mat = (b - 256) >> 8;
        const float* src = (mat == 0) ? q : (mat == 1) ? k : v;

        int tid  = ((b - 256) & 255) * 256 + threadIdx.x;
        int lane = tid & 31;
        int k16  = (tid >> 5) & 15;
        int m16  = tid >> 9;
        int g = lane >> 2, tig = lane & 3;
        int r0 = m16 * 16 + g;
        int r1 = r0 + 8;
        int kb = k16 * 16 + 2 * tig;

        int n0 = r0 >> 10, p0 = r0 & 1023;
        int n1 = r1 >> 10, p1 = r1 & 1023;

        uint32_t hi[4], lo[4];
#pragma unroll
        for (int j = 0; j < 4; j++) {
            int row_n = (j & 1) ? n1 : n0;
            int row_p = (j & 1) ? p1 : p0;
            int kc = kb + ((j >> 1) ? 8 : 0);
            float f0 = src[((size_t)(row_n * 256 + kc)) * 1024 + row_p];
            float f1 = src[((size_t)(row_n * 256 + kc + 1)) * 1024 + row_p];
            float h0, l0, h1, l1;
            split1(f0, h0, l0);
            split1(f1, h1, l1);
            hi[j] = pack2(h0, h1);
            lo[j] = pack2(l0, l1);
        }
        size_t idx = (size_t)mat * AFRAGS + ((size_t)m16 * 16 + k16) * 32 + lane;
        g_Ahi[idx] = make_uint4(hi[0], hi[1], hi[2], hi[3]);
        g_Alo[idx] = make_uint4(lo[0], lo[1], lo[2], lo[3]);
    } else if (b < 1084) {
        int i = (b - 1024) * 256 + threadIdx.x;
        int lane = i & 31;
        int k16  = (i >> 5) & 1;
        int rest = i >> 6;
        int n8 = rest % 30;
        int h  = rest / 30;
        int g = lane >> 2, tig = lane & 3;
        int s240 = n8 * 8 + g;
        int kh = s240 >> 4, kw = s240 & 15;
        int ch = 16 * k16 + 2 * tig;

        float v0 = 0.f, v1 = 0.f, v8 = 0.f, v9 = 0.f;
        if (kw < 15) {
            const float* wr = Wrk + ((size_t)(h * WS2 + kh * WS + kw)) * HDim;
            v0 = T_CONST * wr[ch];
            v1 = T_CONST * wr[ch + 1];
            v8 = T_CONST * wr[ch + 8];
            v9 = T_CONST * wr[ch + 9];
        }
        float h0, l0, h1, l1, h8, l8, h9, l9;
        split1(v0, h0, l0); split1(v1, h1, l1);
        split1(v8, h8, l8); split1(v9, h9, l9);
        size_t idx = ((size_t)(h * 30 + n8) * 2 + k16) * 32 + lane;
        g_WrkFh[idx] = make_uint2(pack2(h0, h1), pack2(h8, h9));
        g_WrkFl[idx] = make_uint2(pack2(l0, l1), pack2(l8, l9));
    } else {
        int i = (b - 1084) * 256 + threadIdx.x;
        if (i < HNUM * WS2 * HDim) {
            int c = i & 31;
            int s = (i >> 5) % WS2;
            int h = i / (WS2 * HDim);
            g_rvT[i] = rel_v[(h * HDim + c) * WS2 + s];
        }
    }
}

// ---------------------------------------------------------------------------
// GEMM half-core: warp computes 16m x 16n over 8 k16 steps starting at k0.
// ---------------------------------------------------------------------------
__device__ __forceinline__ void gemm_core8(
    const uint4* __restrict__ Ahi, const uint4* __restrict__ Alo,
    const uint2* __restrict__ Bhi, const uint2* __restrict__ Blo,
    int m16, int n8b, int lane, int k0, float acc[2][4])
{
#pragma unroll 4
    for (int kk = 0; kk < 8; kk++) {
        const int k16 = k0 + kk;
        uint4 ah = Ahi[((size_t)m16 * 16 + k16) * 32 + lane];
        uint4 al = Alo[((size_t)m16 * 16 + k16) * 32 + lane];
#pragma unroll
        for (int nt = 0; nt < 2; nt++) {
            size_t bi = ((size_t)(n8b + nt) * 16 + k16) * 32 + lane;
            mma3(acc[nt], ah, al, Bhi[bi], Blo[bi]);
        }
    }
}

// ---------------------------------------------------------------------------
// proj_gemm: split-K. grid (64, 8, 3), 256 threads (4 tile-warps x 2 khalf).
// ---------------------------------------------------------------------------
__global__ __launch_bounds__(256) void proj_gemm(
    const float* __restrict__ bQ, const float* __restrict__ bK,
    const float* __restrict__ bV)
{
    __shared__ float red[4][8][32];

    const int mat  = blockIdx.z;
    const int t    = threadIdx.x;
    const int warp = t >> 5;
    const int lane = t & 31;
    const int tile  = warp & 3;
    const int khalf = warp >> 2;
    const int m16  = blockIdx.x * 2 + (tile & 1);
    const int n8b  = (blockIdx.y * 2 + (tile >> 1)) * 2;

    const uint4* Ahi = g_Ahi + (size_t)mat * AFRAGS;
    const uint4* Alo = g_Alo + (size_t)mat * AFRAGS;
    const uint2* Bhi = g_Bhi + (size_t)mat * BFRAGS;
    const uint2* Blo = g_Blo + (size_t)mat * BFRAGS;

    float acc[2][4];
#pragma unroll
    for (int i = 0; i < 2; i++)
#pragma unroll
        for (int j = 0; j < 4; j++) acc[i][j] = 0.f;

    gemm_core8(Ahi, Alo, Bhi, Blo, m16, n8b, lane, khalf * 8, acc);

    if (khalf == 1) {
#pragma unroll
        for (int i = 0; i < 2; i++)
#pragma unroll
            for (int j = 0; j < 4; j++)
                red[tile][i * 4 + j][lane] = acc[i][j];
    }
    __syncthreads();
    if (khalf == 0) {
#pragma unroll
        for (int i = 0; i < 2; i++)
#pragma unroll
            for (int j = 0; j < 4; j++)
                acc[i][j] += red[tile][i * 4 + j][lane];

        const float* b = (mat == 0) ? bQ : (mat == 1) ? bK : bV;
        const int g = lane >> 2, tig = lane & 3;
        const int r0 = m16 * 16 + g;
#pragma unroll
        for (int nt = 0; nt < 2; nt++) {
            const int o0 = (n8b + nt) * 8 + 2 * tig;
            const int h = o0 >> 5, hd = o0 & 31;
            const float b0 = b[o0], b1 = b[o0 + 1];
#pragma unroll
            for (int rr = 0; rr < 2; rr++) {
                const int r = r0 + rr * 8;
                const int n_b = r >> 10, p = r & 1023;
                float vx = acc[nt][rr * 2]     + b0;
                float vy = acc[nt][rr * 2 + 1] + b1;
                if (mat == 0) {
                    float2 val = make_float2(vx * INV_T, vy * INV_T);
                    *(float2*)&g_qs[((size_t)(n_b * HNUM + h) * HW + p) * HDim + hd] = val;
                } else if (mat == 1) {
                    float hx, lx, hy, ly;
                    split1(vx, hx, lx);
                    split1(vy, hy, ly);
                    size_t u = ((size_t)(n_b * HNUM + h) * HW + p) * 16 + (hd >> 1);
                    g_kbf_hi[u] = pack2(hx, hy);
                    g_kbf_lo[u] = pack2(lx, ly);
                } else {
                    float2 val = make_float2(vx, vy);
                    *(float2*)&g_vp[((size_t)(n_b * HNUM + h) * HW + p) * HDim + hd] = val;
                }
            }
        }
    }
}

// ---------------------------------------------------------------------------
// final_gemm: split-K. grid (64, 8), 256 threads.
// ---------------------------------------------------------------------------
__global__ __launch_bounds__(256) void final_gemm(
    const float* __restrict__ bp, float* __restrict__ out)
{
    __shared__ float red[4][8][32];

    const int t    = threadIdx.x;
    const int warp = t >> 5;
    const int lane = t & 31;
    const int tile  = warp & 3;
    const int khalf = warp >> 2;
    const int m16  = blockIdx.x * 2 + (tile & 1);
    const int n8b  = (blockIdx.y * 2 + (tile >> 1)) * 2;

    const uint4* Ahi = g_Ahi + (size_t)3 * AFRAGS;
    const uint4* Alo = g_Alo + (size_t)3 * AFRAGS;
    const uint2* Bhi = g_Bhi + (size_t)3 * BFRAGS;
    const uint2* Blo = g_Blo + (size_t)3 * BFRAGS;

    float acc[2][4];
#pragma unroll
    for (int i = 0; i < 2; i++)
#pragma unroll
        for (int j = 0; j < 4; j++) acc[i][j] = 0.f;

    gemm_core8(Ahi, Alo, Bhi, Blo, m16, n8b, lane, khalf * 8, acc);

    if (khalf == 1) {
#pragma unroll
        for (int i = 0; i < 2; i++)
#pragma unroll
            for (int j = 0; j < 4; j++)
                red[tile][i * 4 + j][lane] = acc[i][j];
    }
    __syncthreads();
    if (khalf == 0) {
#pragma unroll
        for (int i = 0; i < 2; i++)
#pragma unroll
            for (int j = 0; j < 4; j++)
                acc[i][j] += red[tile][i * 4 + j][lane];

        const int g = lane >> 2, tig = lane & 3;
        const int r0 = m16 * 16 + g;
#pragma unroll
        for (int nt = 0; nt < 2; nt++) {
            const int o0 = (n8b + nt) * 8 + 2 * tig;
            const float b0 = bp[o0], b1 = bp[o0 + 1];
#pragma unroll
            for (int rr = 0; rr < 2; rr++) {
                const int r = r0 + rr * 8;
                const int n_b = r >> 10, p = r & 1023;
                float2 val;
                val.x = acc[nt][rr * 2]     + b0;
                val.y = acc[nt][rr * 2 + 1] + b1;
                *(float2*)&out[((size_t)p * NB + n_b) * CCH + o0] = val;
            }
        }
    }
}

// ---------------------------------------------------------------------------
// attn_kernel: grid (32 tiles, 8 heads, 2 batch), 256 threads (8 warps).
// ---------------------------------------------------------------------------
extern __shared__ char smc[];

__global__ __launch_bounds__(256) void attn_kernel(
    const float* __restrict__ brk, float* __restrict__ attn_out)
{
    const int h = blockIdx.y;
    const int n = blockIdx.z;
    const int tileIdx = blockIdx.x;
    const int tx0 = (tileIdx & 3) * TW;
    const int ty0 = (tileIdx >> 2) * TH;
    const int t = threadIdx.x;
    const int w = t >> 5;
    const int lane = t & 31;
    const int g = lane >> 2, tig = lane & 3;
    const int nh = n * HNUM + h;

    uint32_t* kHiU = (uint32_t*)(smc + SM_K);
    uint32_t* kLoU = kHiU + SM_KLO_U;
    float*    vsm  = (float*)(smc + SM_K);
    float*    atsm = (float*)(smc + SM_A);
    float*    sQ   = (float*)(smc + SM_Q);
    float*    sPart = sQ;

    for (int idx = t; idx < TPIX * 32; idx += 256) {
        int px = idx >> 5, c = idx & 31;
        int gp = (ty0 + (px >> 3)) * WDIM + tx0 + (px & 7);
        sQ[px * QSTR + c] = g_qs[((size_t)nh * HW + gp) * HDim + c];
    }
    {
        const uint32_t* kh_hi = g_kbf_hi + (size_t)nh * HW * 16;
        const uint32_t* kh_lo = g_kbf_lo + (size_t)nh * HW * 16;
        for (int idx = t; idx < NHALO_P * 16; idx += 256) {
            int hp = idx >> 4, c2 = idx & 15;
            uint32_t vh = 0, vl = 0;
            if (hp < NHALO) {
                int hy = hp / HC, hx = hp - hy * HC;
                int gy = ty0 - MAXDIS + hy, gx = tx0 - MAXDIS + hx;
                if ((unsigned)gy < 32u && (unsigned)gx < 32u) {
                    size_t off = (size_t)(gy * WDIM + gx) * 16 + c2;
                    vh = kh_hi[off];
                    vl = kh_lo[off];
                }
            }
            kHiU[hp * KROWU + c2] = vh;
            kLoU[hp * KROWU + c2] = vl;
        }
    }
    __syncthreads();

    // ---- build Q A-fragments: 2 m16 x 2 k16 ----
    uint4 aQh[2][2], aQl[2][2];
#pragma unroll
    for (int m16 = 0; m16 < 2; m16++) {
#pragma unroll
        for (int k16 = 0; k16 < 2; k16++) {
            int rb = m16 * 16 + g;
            int kb = 16 * k16 + 2 * tig;
            float v00 = sQ[rb * QSTR + kb],            v01 = sQ[rb * QSTR + kb + 1];
            float v10 = sQ[(rb + 8) * QSTR + kb],      v11 = sQ[(rb + 8) * QSTR + kb + 1];
            float v08 = sQ[rb * QSTR + kb + 8],        v09 = sQ[rb * QSTR + kb + 9];
            float v18 = sQ[(rb + 8) * QSTR + kb + 8],  v19 = sQ[(rb + 8) * QSTR + kb + 9];
            float h00,l00,h01,l01,h10,l10,h11,l11,h08,l08,h09,l09,h18,l18,h19,l19;
            split1(v00,h00,l00); split1(v01,h01,l01);
            split1(v10,h10,l10); split1(v11,h11,l11);
            split1(v08,h08,l08); split1(v09,h09,l09);
            split1(v18,h18,l18); split1(v19,h19,l19);
            aQh[m16][k16] = make_uint4(pack2(h00,h01), pack2(h10,h11),
                                       pack2(h08,h09), pack2(h18,h19));
            aQl[m16][k16] = make_uint4(pack2(l00,l01), pack2(l10,l11),
                                       pack2(l08,l09), pack2(l18,l19));
        }
    }

    // ---- phase R: rel logits GEMM -> atsm ----
    for (int n8 = w; n8 < 30; n8 += 8) {
        float acc[2][4];
#pragma unroll
        for (int i = 0; i < 2; i++)
#pragma unroll
            for (int j = 0; j < 4; j++) acc[i][j] = 0.f;
#pragma unroll
        for (int k16 = 0; k16 < 2; k16++) {
            size_t bi = ((size_t)(h * 30 + n8) * 2 + k16) * 32 + lane;
            uint2 bh = g_WrkFh[bi];
            uint2 bl = g_WrkFl[bi];
            mma3(acc[0], aQh[0][k16], aQl[0][k16], bh, bl);
            mma3(acc[1], aQh[1][k16], aQl[1][k16], bh, bl);
        }
        const int c0 = n8 * 8 + 2 * tig;
        const int kh = c0 >> 4, kw = c0 & 15;
        float bb0 = (kw < 15) ? brk[h * WS2 + kh * WS + kw] : 0.f;
        float bb1 = (kw < 14) ? brk[h * WS2 + kh * WS + kw + 1] : 0.f;
#pragma unroll
        for (int m16 = 0; m16 < 2; m16++) {
            const int rb = m16 * 16 + g;
            atsm[rb * ASTR + c0]           = acc[m16][0] + bb0;
            atsm[rb * ASTR + c0 + 1]       = acc[m16][1] + bb1;
            atsm[(rb + 8) * ASTR + c0]     = acc[m16][2] + bb0;
            atsm[(rb + 8) * ASTR + c0 + 1] = acc[m16][3] + bb1;
        }
    }
    __syncthreads();

    // ---- phase S: dense QK GEMM + banded scatter ----
    for (int n8 = w; n8 < 50; n8 += 8) {
        float acc[2][4];
#pragma unroll
        for (int i = 0; i < 2; i++)
#pragma unroll
            for (int j = 0; j < 4; j++) acc[i][j] = 0.f;
#pragma unroll
        for (int k16 = 0; k16 < 2; k16++) {
            int bi = (n8 * 8 + g) * KROWU + 8 * k16 + tig;
            uint2 bh = make_uint2(kHiU[bi], kHiU[bi + 4]);
            uint2 bl = make_uint2(kLoU[bi], kLoU[bi + 4]);
            mma3(acc[0], aQh[0][k16], aQl[0][k16], bh, bl);
            mma3(acc[1], aQh[1][k16], aQl[1][k16], bh, bl);
        }
        const int c0 = n8 * 8 + 2 * tig;
#pragma unroll
        for (int m16 = 0; m16 < 2; m16++) {
#pragma unroll
            for (int j = 0; j < 4; j++) {
                const int row = m16 * 16 + g + ((j >> 1) ? 8 : 0);
                const int cc  = c0 + (j & 1);
                if (cc < NHALO) {
                    const int hy = cc / HC, hx = cc - hy * HC;
                    const int py = row >> 3, pxx = row & 7;
                    const int kh = hy - py, kw = hx - pxx;
                    if ((unsigned)kh < 15u && (unsigned)kw < 15u) {
                        const int gy = ty0 + hy - MAXDIS;
                        const int gx = tx0 + hx - MAXDIS;
                        const int idx = row * ASTR + kh * 16 + kw;
                        float a = atsm[idx] + acc[m16][j];
                        if (!((unsigned)gy < 32u && (unsigned)gx < 32u))
                            a -= 1e8f;
                        atsm[idx] = a;
                    }
                }
            }
        }
    }
    __syncthreads();

    // ---- load V fp32 (overwrites K region) ----
    for (int i4 = t; i4 < NHALO * 8; i4 += 256) {
        int hp = i4 >> 3, c4 = (i4 & 7) * 4;
        int hy = hp / HC, hx = hp - hy * HC;
        int gy = ty0 - MAXDIS + hy, gx = tx0 - MAXDIS + hx;
        float4 vv = make_float4(0.f, 0.f, 0.f, 0.f);
        if ((unsigned)gy < 32u && (unsigned)gx < 32u)
            vv = *(const float4*)&g_vp[((size_t)nh * HW + gy * WDIM + gx) * HDim + c4];
        *(float4*)&vsm[hp * KSTR + c4] = vv;
    }

    // ---- softmax ----
    {
#pragma unroll
        for (int pp = 0; pp < 4; pp++) {
            const int px = w * 4 + pp;
            float* arow = &atsm[px * ASTR];
            if (lane < 15) arow[lane * 16 + 15] = 0.f;
            float vals[8];
            int   offs[8];
            float mx = -3.4e38f;
#pragma unroll
            for (int i = 0; i < 8; i++) {
                int s = lane + 32 * i;
                if (s < WS2) {
                    offs[i] = (s / WS) * 16 + (s % WS);
                    vals[i] = arow[offs[i]];
                } else { offs[i] = -1; vals[i] = -3.4e38f; }
                mx = fmaxf(mx, vals[i]);
            }
#pragma unroll
            for (int off = 16; off; off >>= 1)
                mx = fmaxf(mx, __shfl_xor_sync(0xffffffffu, mx, off));
            float sum = 0.f;
#pragma unroll
            for (int i = 0; i < 8; i++) {
                float e = (offs[i] >= 0) ? __expf(vals[i] - mx) : 0.f;
                vals[i] = e;
                sum += e;
            }
#pragma unroll
            for (int off = 16; off; off >>= 1)
                sum += __shfl_xor_sync(0xffffffffu, sum, off);
            const float inv = 1.0f / sum;
#pragma unroll
            for (int i = 0; i < 8; i++)
                if (offs[i] >= 0) arow[offs[i]] = vals[i] * inv;
        }
    }
    __syncthreads();

    // ---- write attn probabilities ----
    if (attn_out) {
        float* ao = attn_out + (size_t)nh * WS2 * HW;
        for (int idx = t; idx < WS2 * TPIX; idx += 256) {
            int px = idx & 31, s = idx >> 5;
            int off = (s / WS) * 16 + (s % WS);
            int pgl = (ty0 + (px >> 3)) * WDIM + tx0 + (px & 7);
            ao[s * HW + pgl] = atsm[px * ASTR + off];
        }
    }

    // ---- output: sliding-window regs; scatter into A-fragments ----
    {
        const int c    = t & 31;
        const int warp = t >> 5;
        const int py   = warp & 3;
        const int half = warp >> 2;
        const int kh0  = half ? 8 : 0;
        const int kh1  = half ? 15 : 8;
        const float* rvh = g_rvT + (size_t)h * WS2 * HDim;

        float acc[TW];
#pragma unroll
        for (int i = 0; i < TW; i++) acc[i] = 0.f;

        for (int kh = kh0; kh < kh1; kh++) {
            const int hy = py + kh;
            float vreg[HC];
#pragma unroll
            for (int x = 0; x < HC; x++)
                vreg[x] = vsm[(hy * HC + x) * KSTR + c];
            float rreg[WS];
#pragma unroll
            for (int kw = 0; kw < WS; kw++)
                rreg[kw] = rvh[(kh * WS + kw) * HDim + c];

#pragma unroll
            for (int pxx = 0; pxx < TW; pxx++) {
                const float* arow = &atsm[(py * TW + pxx) * ASTR + kh * 16];
                float4 a0 = *(const float4*)(arow);
                float4 a1 = *(const float4*)(arow + 4);
                float4 a2 = *(const float4*)(arow + 8);
                float4 a3 = *(const float4*)(arow + 12);
                float av[15] = {a0.x, a0.y, a0.z, a0.w, a1.x, a1.y, a1.z, a1.w,
                                a2.x, a2.y, a2.z, a2.w, a3.x, a3.y, a3.z};
                float s0 = 0.f;
#pragma unroll
                for (int kw = 0; kw < WS; kw++) {
                    acc[pxx] += av[kw] * vreg[pxx + kw];
                    s0       += av[kw] * rreg[kw];
                }
                acc[pxx] += s0;
            }
        }

        if (half == 1) {
#pragma unroll
            for (int pxx = 0; pxx < TW; pxx++)
                sPart[(py * TW + pxx) * 32 + c] = acc[pxx];
        }
        __syncthreads();
        if (half == 0) {
            const int kglobal = h * 32 + c;
            const int k16  = kglobal >> 4;
            const int w16  = kglobal & 15;
            const int tigf = (w16 & 7) >> 1;
            const int jhi  = (w16 >> 3) & 1;
            uint32_t* AhiU = (uint32_t*)g_Ahi;
            uint32_t* AloU = (uint32_t*)g_Alo;
#pragma unroll
            for (int pxx = 0; pxx < TW; pxx++) {
                const int gy = ty0 + py, gx = tx0 + pxx;
                float tot = acc[pxx] + sPart[(py * TW + pxx) * 32 + c];
                float totN = __shfl_xor_sync(0xffffffffu, tot, 1);
                if ((c & 1) == 0) {
                    float hiE, loE, hiO, loO;
                    split1(tot,  hiE, loE);
                    split1(totN, hiO, loO);
                    const int m = n * HW + gy * WDIM + gx;
                    const int j = jhi * 2 + ((m >> 3) & 1);
                    const int lanef = (m & 7) * 4 + tigf;
                    const size_t u =
                        ((size_t)(3 * AFRAGS)
                         + ((size_t)(m >> 4) * 16 + k16) * 32 + lanef) * 4 + j;
                    AhiU[u] = pack2(hiE, hiO);
                    AloU[u] = pack2(loE, loO);
                }
            }
        }
    }
}

// ---------------------------------------------------------------------------
extern "C" void kernel_launch(void* const* d_in, const int* in_sizes, int n_in,
                              void* d_out, int out_size)
{
    const float* q     = (const float*)d_in[0];
    const float* k     = (const float*)d_in[1];
    const float* v     = (const float*)d_in[2];
    const float* WQ    = (const float*)d_in[3];
    const float* bQ    = (const float*)d_in[4];
    const float* WK    = (const float*)d_in[5];
    const float* bK    = (const float*)d_in[6];
    const float* WV    = (const float*)d_in[7];
    const float* bV    = (const float*)d_in[8];
    const float* Wrk   = (const float*)d_in[9];
    const float* brk   = (const float*)d_in[10];
    const float* rel_v = (const float*)d_in[11];
    const float* Wp    = (const float*)d_in[12];
    const float* bp    = (const float*)d_in[13];

    float* out = (float*)d_out;
    float* attn_out = nullptr;
    if (out_size >= OUT_ELEMS + ATTN_ELEMS)
        attn_out = out + OUT_ELEMS;

    cudaFuncSetAttribute(attn_kernel,
                         cudaFuncAttributeMaxDynamicSharedMemorySize, SMEM_ATTN);

    prep_all<<<1309, 256>>>(q, k, v, WQ, WK, WV, Wp, Wrk, rel_v);
    proj_gemm<<<dim3(64, 8, 3), 256>>>(bQ, bK, bV);
    attn_kernel<<<dim3(32, HNUM, NB), 256, SMEM_ATTN>>>(brk, attn_out);
    final_gemm<<<dim3(64, 8), 256>>>(bp, out);
}